// round 7
// baseline (speedup 1.0000x reference)
#include <cuda_runtime.h>
#include <cuda_bf16.h>
#include <cuda_fp16.h>
#include <cstdint>

#define D_MODEL 1024
#define N_HEADS 16
#define D_HEAD  64
#define BATCH   2
#define SEQ     2048
#define M_ROWS  (BATCH * SEQ)      // 4096

// Q pre-scale: 1/sqrt(Dh) * log2(e)  (softmax computed in exp2 domain)
#define QSCALE 0.1803368801111204f

// ---------------- scratch (no allocations allowed) ----------------
__device__ __half g_Qh[(size_t)BATCH * N_HEADS * SEQ * D_HEAD];
__device__ __half g_Ql[(size_t)BATCH * N_HEADS * SEQ * D_HEAD];
__device__ __half g_Kh[(size_t)BATCH * N_HEADS * SEQ * D_HEAD];
__device__ __half g_Kl[(size_t)BATCH * N_HEADS * SEQ * D_HEAD];
__device__ __half g_Vh[(size_t)BATCH * N_HEADS * SEQ * D_HEAD];
__device__ __half g_Vl[(size_t)BATCH * N_HEADS * SEQ * D_HEAD];

__device__ __nv_bfloat16 g_xh[(size_t)M_ROWS * D_MODEL];
__device__ __nv_bfloat16 g_xl[(size_t)M_ROWS * D_MODEL];
__device__ __nv_bfloat16 g_Ah[(size_t)M_ROWS * D_MODEL];
__device__ __nv_bfloat16 g_Al[(size_t)M_ROWS * D_MODEL];
__device__ __nv_bfloat16 g_Wth[(size_t)4 * D_MODEL * D_MODEL];  // W^T hi, [4][n][k]
__device__ __nv_bfloat16 g_Wtl[(size_t)4 * D_MODEL * D_MODEL];  // W^T lo

// ---------------- helpers ----------------
__device__ __forceinline__ uint32_t smem_u32(const void* p) {
    uint32_t a;
    asm("{ .reg .u64 t; cvta.to.shared.u64 t, %1; cvt.u32.u64 %0, t; }" : "=r"(a) : "l"(p));
    return a;
}
__device__ __forceinline__ void cp_async16(uint32_t sa, const void* g) {
    asm volatile("cp.async.cg.shared.global [%0], [%1], 16;\n" :: "r"(sa), "l"(g));
}
__device__ __forceinline__ void ldmat4(uint32_t* r, uint32_t addr) {
    asm volatile("ldmatrix.sync.aligned.m8n8.x4.shared.b16 {%0,%1,%2,%3}, [%4];"
        : "=r"(r[0]), "=r"(r[1]), "=r"(r[2]), "=r"(r[3]) : "r"(addr));
}
__device__ __forceinline__ void ldmat4t(uint32_t* r, uint32_t addr) {
    asm volatile("ldmatrix.sync.aligned.m8n8.x4.trans.shared.b16 {%0,%1,%2,%3}, [%4];"
        : "=r"(r[0]), "=r"(r[1]), "=r"(r[2]), "=r"(r[3]) : "r"(addr));
}
__device__ __forceinline__ void mma_bf(float* c, const uint32_t* a, const uint32_t* b) {
    asm volatile("mma.sync.aligned.m16n8k16.row.col.f32.bf16.bf16.f32 "
        "{%0,%1,%2,%3}, {%4,%5,%6,%7}, {%8,%9}, {%0,%1,%2,%3};"
        : "+f"(c[0]), "+f"(c[1]), "+f"(c[2]), "+f"(c[3])
        : "r"(a[0]), "r"(a[1]), "r"(a[2]), "r"(a[3]), "r"(b[0]), "r"(b[1]));
}
__device__ __forceinline__ void mma_fp(float* c, const uint32_t* a, const uint32_t* b) {
    asm volatile("mma.sync.aligned.m16n8k16.row.col.f32.f16.f16.f32 "
        "{%0,%1,%2,%3}, {%4,%5,%6,%7}, {%8,%9}, {%0,%1,%2,%3};"
        : "+f"(c[0]), "+f"(c[1]), "+f"(c[2]), "+f"(c[3])
        : "r"(a[0]), "r"(a[1]), "r"(a[2]), "r"(a[3]), "r"(b[0]), "r"(b[1]));
}
__device__ __forceinline__ float fexp2(float x) {
    float r; asm("ex2.approx.f32 %0, %1;" : "=f"(r) : "f"(x)); return r;
}
__device__ __forceinline__ uint32_t pack_h2(float a, float b) {
    __half2 h = __halves2half2(__float2half_rn(a), __float2half_rn(b));
    union { __half2 h2; uint32_t u; } c; c.h2 = h; return c.u;
}

// ---------------- conversion kernels ----------------
__global__ __launch_bounds__(256) void cvt_rm(const float* __restrict__ src)
{
    const size_t i4 = (size_t)blockIdx.x * blockDim.x + threadIdx.x;
    if (i4 < (size_t)M_ROWS * D_MODEL / 4) {
        float4 v = ((const float4*)src)[i4];
        float vv[4] = {v.x, v.y, v.z, v.w};
#pragma unroll
        for (int j = 0; j < 4; j++) {
            __nv_bfloat16 h = __float2bfloat16_rn(vv[j]);
            g_xh[i4 * 4 + j] = h;
            g_xl[i4 * 4 + j] = __float2bfloat16_rn(vv[j] - __bfloat162float(h));
        }
    }
}

__global__ __launch_bounds__(256) void cvt_wt(const float* __restrict__ Wq,
                                              const float* __restrict__ Wk,
                                              const float* __restrict__ Wv,
                                              const float* __restrict__ Wo)
{
    __shared__ float t[32][33];
    const int z = blockIdx.z;
    const float* W = (z == 0) ? Wq : (z == 1) ? Wk : (z == 2) ? Wv : Wo;
    __nv_bfloat16* hi = g_Wth + (size_t)z * D_MODEL * D_MODEL;
    __nv_bfloat16* lo = g_Wtl + (size_t)z * D_MODEL * D_MODEL;
    const int n0 = blockIdx.x * 32, k0 = blockIdx.y * 32;
    const int tx = threadIdx.x & 31, ty = threadIdx.x >> 5;
    for (int r = ty; r < 32; r += 8)
        t[r][tx] = W[(size_t)(k0 + r) * D_MODEL + n0 + tx];
    __syncthreads();
    for (int r = ty; r < 32; r += 8) {
        float v = t[tx][r];
        __nv_bfloat16 h = __float2bfloat16_rn(v);
        const size_t o = (size_t)(n0 + r) * D_MODEL + k0 + tx;
        hi[o] = h;
        lo[o] = __float2bfloat16_rn(v - __bfloat162float(h));
    }
}

// ---------------- mma.sync split-bf16 GEMM ----------------
#define AST   40
#define TILEB (128 * AST * 2)
#define BUFB  (4 * TILEB)
#define KC    32
#define NKC   (D_MODEL / KC)

__device__ __forceinline__ void load_chunk_mma(uint32_t bufbase, int c, int tid,
        const __nv_bfloat16* g0, const __nv_bfloat16* g1,
        const __nv_bfloat16* g2, const __nv_bfloat16* g3)
{
    const __nv_bfloat16* gs[4] = {g0, g1, g2, g3};
#pragma unroll
    for (int i = 0; i < 8; i++) {
        const int idx = i * 256 + tid;
        const int t = idx >> 9;
        const int rem = idx & 511;
        const int row = rem >> 2;
        const int seg = rem & 3;
        const __nv_bfloat16* g = gs[t] + (size_t)row * D_MODEL + c * KC + seg * 8;
        cp_async16(bufbase + t * TILEB + row * (AST * 2) + seg * 16, g);
    }
    asm volatile("cp.async.commit_group;\n" ::: "memory");
}

__global__ __launch_bounds__(256, 1) void gemm_mma(
        const float* __restrict__ bq, const float* __restrict__ bk,
        const float* __restrict__ bv, float* __restrict__ out, int mode)
{
    extern __shared__ char smem[];
    const uint32_t sb = smem_u32(smem);
    const int tid = threadIdx.x;
    const int wid = tid >> 5, lane = tid & 31;
    const int wy = wid & 3, wx = wid >> 2;
    const int rowBase = blockIdx.y * 128;
    const int colBase = blockIdx.x * 128;
    const int z = (mode == 0) ? blockIdx.z : 3;

    const __nv_bfloat16* Ah = ((mode == 0) ? g_xh : g_Ah) + (size_t)rowBase * D_MODEL;
    const __nv_bfloat16* Al = ((mode == 0) ? g_xl : g_Al) + (size_t)rowBase * D_MODEL;
    const __nv_bfloat16* Bh = g_Wth + (size_t)z * D_MODEL * D_MODEL + (size_t)colBase * D_MODEL;
    const __nv_bfloat16* Bl = g_Wtl + (size_t)z * D_MODEL * D_MODEL + (size_t)colBase * D_MODEL;

    const uint32_t buf0 = sb, buf1 = sb + BUFB;

    float acc[2][8][4];
#pragma unroll
    for (int mt = 0; mt < 2; mt++)
#pragma unroll
        for (int nt = 0; nt < 8; nt++)
#pragma unroll
            for (int j = 0; j < 4; j++) acc[mt][nt][j] = 0.f;

    load_chunk_mma(buf0, 0, tid, Ah, Al, Bh, Bl);
    load_chunk_mma(buf1, 1, tid, Ah, Al, Bh, Bl);

    const int arow = (lane & 7) + ((lane >> 3) & 1) * 8;
    const int acol = (lane >> 4) * 8;
    const int brow = (lane & 7) + (lane >> 4) * 8;
    const int bcol = ((lane >> 3) & 1) * 8;

    for (int c = 0; c < NKC; c++) {
        const int b = c & 1;
        if (c < NKC - 1) asm volatile("cp.async.wait_group 1;\n" ::: "memory");
        else             asm volatile("cp.async.wait_group 0;\n" ::: "memory");
        __syncthreads();

        const uint32_t base = b ? buf1 : buf0;
        const uint32_t aHs = base,             aLs = base + TILEB;
        const uint32_t bHs = base + 2 * TILEB, bLs = base + 3 * TILEB;

#pragma unroll
        for (int ks = 0; ks < 2; ks++) {
            uint32_t ah[2][4], al[2][4], bh[4][4], bl[4][4];
#pragma unroll
            for (int mt = 0; mt < 2; mt++) {
                const uint32_t off = (uint32_t)(wy * 32 + mt * 16 + arow) * (AST * 2)
                                   + (uint32_t)(ks * 16 + acol) * 2;
                ldmat4(ah[mt], aHs + off);
                ldmat4(al[mt], aLs + off);
            }
#pragma unroll
            for (int np = 0; np < 4; np++) {
                const uint32_t off = (uint32_t)(wx * 64 + np * 16 + brow) * (AST * 2)
                                   + (uint32_t)(ks * 16 + bcol) * 2;
                ldmat4(bh[np], bHs + off);
                ldmat4(bl[np], bLs + off);
            }
            // pass-major order: each pass touches 16 distinct accumulators
            // before any target repeats (kills the RAW chains).
#pragma unroll
            for (int mt = 0; mt < 2; mt++)
#pragma unroll
                for (int np = 0; np < 4; np++) {
                    mma_bf(acc[mt][np * 2],     ah[mt], &bh[np][0]);
                    mma_bf(acc[mt][np * 2 + 1], ah[mt], &bh[np][2]);
                }
#pragma unroll
            for (int mt = 0; mt < 2; mt++)
#pragma unroll
                for (int np = 0; np < 4; np++) {
                    mma_bf(acc[mt][np * 2],     ah[mt], &bl[np][0]);
                    mma_bf(acc[mt][np * 2 + 1], ah[mt], &bl[np][2]);
                }
#pragma unroll
            for (int mt = 0; mt < 2; mt++)
#pragma unroll
                for (int np = 0; np < 4; np++) {
                    mma_bf(acc[mt][np * 2],     al[mt], &bh[np][0]);
                    mma_bf(acc[mt][np * 2 + 1], al[mt], &bh[np][2]);
                }
        }
        __syncthreads();
        if (c + 2 < NKC)
            load_chunk_mma(b ? buf1 : buf0, c + 2, tid, Ah, Al, Bh, Bl);
    }

    // ---------------- epilogue ----------------
    if (mode == 0) {
        const float* bias = (z == 0) ? bq : (z == 1) ? bk : bv;
        __half* dH = (z == 0) ? g_Qh : (z == 1) ? g_Kh : g_Vh;
        __half* dL = (z == 0) ? g_Ql : (z == 1) ? g_Kl : g_Vl;
        const float sc = (z == 0) ? QSCALE : 1.0f;
#pragma unroll
        for (int mt = 0; mt < 2; mt++) {
#pragma unroll
            for (int nt = 0; nt < 8; nt++) {
                const int col0 = colBase + wx * 64 + nt * 8 + (lane & 3) * 2;
                const int hh = col0 >> 6, d0 = col0 & (D_HEAD - 1);
                const float b0 = bias[col0], b1 = bias[col0 + 1];
#pragma unroll
                for (int half_m = 0; half_m < 2; half_m++) {
                    const int row = rowBase + wy * 32 + mt * 16 + (lane >> 2) + half_m * 8;
                    const int bb = row >> 11, s = row & (SEQ - 1);
                    float v0 = (acc[mt][nt][half_m * 2]     + b0) * sc;
                    float v1 = (acc[mt][nt][half_m * 2 + 1] + b1) * sc;
                    __half h0 = __float2half_rn(v0), h1 = __float2half_rn(v1);
                    __half l0 = __float2half_rn(v0 - __half2float(h0));
                    __half l1 = __float2half_rn(v1 - __half2float(h1));
                    const size_t e = (((size_t)(bb * N_HEADS + hh)) * SEQ + s) * D_HEAD + d0;
                    *(__half2*)(dH + e) = __halves2half2(h0, h1);
                    *(__half2*)(dL + e) = __halves2half2(l0, l1);
                }
            }
        }
    } else {
#pragma unroll
        for (int mt = 0; mt < 2; mt++)
#pragma unroll
            for (int nt = 0; nt < 8; nt++)
#pragma unroll
                for (int j = 0; j < 4; j++) {
                    const int row = rowBase + wy * 32 + mt * 16 + (lane >> 2) + (j >> 1) * 8;
                    const int col = colBase + wx * 64 + nt * 8 + (lane & 3) * 2 + (j & 1);
                    out[(size_t)row * D_MODEL + col] = acc[mt][nt][j];
                }
    }
}

// ---------------- tensor-core flash attention ----------------
// CTA: 256 thr / 8 warps; BQ=128 (16 rows per warp), BK=64.
// S = qh*kh + ql*kh + qh*kl ; PV = ph*vh + ph*vl + pl*vh
#define FBK    64
#define FST    72                      // smem row stride in halves
#define QTILE  (128 * FST)             // halves
#define KTILE  (64 * FST)              // halves

__device__ __forceinline__ void load_kv(__half* stagep, int kb, int tid,
        const __half* gKh, const __half* gKl, const __half* gVh, const __half* gVl)
{
    const __half* gs[4] = {gKh, gKl, gVh, gVl};
#pragma unroll
    for (int i = 0; i < 8; i++) {
        const int idx = i * 256 + tid;
        const int t = idx >> 9;
        const int rem = idx & 511;
        const int row = rem >> 3;
        const int seg = rem & 7;
        const __half* g = gs[t] + (size_t)(kb + row) * D_HEAD + seg * 8;
        cp_async16(smem_u32(stagep + t * KTILE + row * FST + seg * 8), g);
    }
    asm volatile("cp.async.commit_group;\n" ::: "memory");
}

__global__ __launch_bounds__(256, 1) void flash_mma()
{
    extern __shared__ __half fsm[];
    const int tid = threadIdx.x;
    const int wid = tid >> 5, lane = tid & 31;
    const int qt = blockIdx.x, h = blockIdx.y, b = blockIdx.z;
    const int bh = b * N_HEADS + h;
    const int qBase = qt * 128;
    const size_t gbase = (size_t)bh * SEQ * D_HEAD;

    const __half* gQh = g_Qh + gbase;
    const __half* gQl = g_Ql + gbase;
    const __half* gKh = g_Kh + gbase;
    const __half* gKl = g_Kl + gbase;
    const __half* gVh = g_Vh + gbase;
    const __half* gVl = g_Vl + gbase;

    __half* sQh = fsm;
    __half* sQl = fsm + QTILE;
    __half* stage0 = fsm + 2 * QTILE;
    __half* stage1 = stage0 + 4 * KTILE;

    // Q tile load (group 0)
#pragma unroll
    for (int i = 0; i < 8; i++) {
        const int idx = i * 256 + tid;
        const int t = idx >> 10;
        const int rem = idx & 1023;
        const int row = rem >> 3;
        const int seg = rem & 7;
        const __half* g = (t ? gQl : gQh) + (size_t)(qBase + row) * D_HEAD + seg * 8;
        cp_async16(smem_u32((t ? sQl : sQh) + row * FST + seg * 8), g);
    }
    asm volatile("cp.async.commit_group;\n" ::: "memory");

    const int nkt = 2 * (qt + 1);
    load_kv(stage0, 0, tid, gKh, gKl, gVh, gVl);
    load_kv(stage1, FBK, tid, gKh, gKl, gVh, gVl);

    const int arow = (lane & 7) + ((lane >> 3) & 1) * 8;
    const int acol = (lane >> 4) * 8;
    // non-trans B pattern (K): rows = n (keys), cols = k (d)
    const int brow = (lane & 7) + (lane >> 4) * 8;
    const int bcol = ((lane >> 3) & 1) * 8;
    // trans B pattern (V): rows = k (s), cols = n (d)
    const int trow = (lane & 7) + ((lane >> 3) & 1) * 8;
    const int tcol = (lane >> 4) * 8;

    uint32_t qh[4][4], ql[4][4];
    float o[8][4];
#pragma unroll
    for (int nb = 0; nb < 8; nb++)
#pragma unroll
        for (int j = 0; j < 4; j++) o[nb][j] = 0.f;
    float m0 = -1e30f, m1 = -1e30f, l0 = 0.f, l1 = 0.f;

    const int row0 = qBase + wid * 16 + (lane >> 2);
    const int row1 = row0 + 8;

    for (int jt = 0; jt < nkt; jt++) {
        __half* stg = (jt & 1) ? stage1 : stage0;
        if (jt < nkt - 1) asm volatile("cp.async.wait_group 1;\n" ::: "memory");
        else              asm volatile("cp.async.wait_group 0;\n" ::: "memory");
        __syncthreads();

        if (jt == 0) {
#pragma unroll
            for (int kk = 0; kk < 4; kk++) {
                const uint32_t off = (uint32_t)(wid * 16 + arow) * (FST * 2)
                                   + (uint32_t)(kk * 16 + acol) * 2;
                ldmat4(qh[kk], smem_u32(sQh) + off);
                ldmat4(ql[kk], smem_u32(sQl) + off);
            }
        }

        const uint32_t sKh = smem_u32(stg);
        const uint32_t sKl = sKh + KTILE * 2;
        const uint32_t sVh = sKh + 2 * KTILE * 2;
        const uint32_t sVl = sKh + 3 * KTILE * 2;

        float s[8][4];
#pragma unroll
        for (int nb = 0; nb < 8; nb++)
#pragma unroll
            for (int j = 0; j < 4; j++) s[nb][j] = 0.f;

        // ---- S = Q K^T : pass-major, 8 distinct targets per pass ----
#pragma unroll
        for (int kk = 0; kk < 4; kk++) {
            uint32_t bkh[4][4], bkl[4][4];
#pragma unroll
            for (int np = 0; np < 4; np++) {
                const uint32_t off = (uint32_t)(np * 16 + brow) * (FST * 2)
                                   + (uint32_t)(kk * 16 + bcol) * 2;
                ldmat4(bkh[np], sKh + off);
                ldmat4(bkl[np], sKl + off);
            }
#pragma unroll
            for (int np = 0; np < 4; np++) {
                mma_fp(s[np * 2],     qh[kk], &bkh[np][0]);
                mma_fp(s[np * 2 + 1], qh[kk], &bkh[np][2]);
            }
#pragma unroll
            for (int np = 0; np < 4; np++) {
                mma_fp(s[np * 2],     ql[kk], &bkh[np][0]);
                mma_fp(s[np * 2 + 1], ql[kk], &bkh[np][2]);
            }
#pragma unroll
            for (int np = 0; np < 4; np++) {
                mma_fp(s[np * 2],     qh[kk], &bkl[np][0]);
                mma_fp(s[np * 2 + 1], qh[kk], &bkl[np][2]);
            }
        }

        // ---- causal mask (partial tiles only) ----
        if (jt >= 2 * qt) {
            const int kb = jt * FBK;
#pragma unroll
            for (int nb = 0; nb < 8; nb++) {
#pragma unroll
                for (int j = 0; j < 4; j++) {
                    const int key = kb + nb * 8 + (lane & 3) * 2 + (j & 1);
                    const int qr = (j < 2) ? row0 : row1;
                    if (key > qr) s[nb][j] = -1e30f;
                }
            }
        }

        // ---- online softmax (exp2 domain) ----
        float mx0 = -1e30f, mx1 = -1e30f;
#pragma unroll
        for (int nb = 0; nb < 8; nb++) {
            mx0 = fmaxf(mx0, fmaxf(s[nb][0], s[nb][1]));
            mx1 = fmaxf(mx1, fmaxf(s[nb][2], s[nb][3]));
        }
        mx0 = fmaxf(mx0, __shfl_xor_sync(0xffffffffu, mx0, 1));
        mx0 = fmaxf(mx0, __shfl_xor_sync(0xffffffffu, mx0, 2));
        mx1 = fmaxf(mx1, __shfl_xor_sync(0xffffffffu, mx1, 1));
        mx1 = fmaxf(mx1, __shfl_xor_sync(0xffffffffu, mx1, 2));
        const float mn0 = fmaxf(m0, mx0), mn1 = fmaxf(m1, mx1);
        const float c0 = fexp2(m0 - mn0), c1 = fexp2(m1 - mn1);
        m0 = mn0; m1 = mn1;

        float sum0 = 0.f, sum1 = 0.f;
#pragma unroll
        for (int nb = 0; nb < 8; nb++) {
            s[nb][0] = fexp2(s[nb][0] - m0); sum0 += s[nb][0];
            s[nb][1] = fexp2(s[nb][1] - m0); sum0 += s[nb][1];
            s[nb][2] = fexp2(s[nb][2] - m1); sum1 += s[nb][2];
            s[nb][3] = fexp2(s[nb][3] - m1); sum1 += s[nb][3];
        }
        sum0 += __shfl_xor_sync(0xffffffffu, sum0, 1);
        sum0 += __shfl_xor_sync(0xffffffffu, sum0, 2);
        sum1 += __shfl_xor_sync(0xffffffffu, sum1, 1);
        sum1 += __shfl_xor_sync(0xffffffffu, sum1, 2);
        l0 = l0 * c0 + sum0;
        l1 = l1 * c1 + sum1;

#pragma unroll
        for (int nb = 0; nb < 8; nb++) {
            o[nb][0] *= c0; o[nb][1] *= c0;
            o[nb][2] *= c1; o[nb][3] *= c1;
        }

        // ---- O += P V : pass-major, 8 distinct targets per pass ----
#pragma unroll
        for (int kk = 0; kk < 4; kk++) {
            uint32_t aH[4], aL[4];
            aH[0] = pack_h2(s[2 * kk][0], s[2 * kk][1]);
            aH[1] = pack_h2(s[2 * kk][2], s[2 * kk][3]);
            aH[2] = pack_h2(s[2 * kk + 1][0], s[2 * kk + 1][1]);
            aH[3] = pack_h2(s[2 * kk + 1][2], s[2 * kk + 1][3]);
            {
                union { uint32_t u; __half2 h2; } c0u, c1u, c2u, c3u;
                c0u.u = aH[0]; c1u.u = aH[1]; c2u.u = aH[2]; c3u.u = aH[3];
                aL[0] = pack_h2(s[2 * kk][0] - __half2float(__low2half(c0u.h2)),
                                s[2 * kk][1] - __half2float(__high2half(c0u.h2)));
                aL[1] = pack_h2(s[2 * kk][2] - __half2float(__low2half(c1u.h2)),
                                s[2 * kk][3] - __half2float(__high2half(c1u.h2)));
                aL[2] = pack_h2(s[2 * kk + 1][0] - __half2float(__low2half(c2u.h2)),
                                s[2 * kk + 1][1] - __half2float(__high2half(c2u.h2)));
                aL[3] = pack_h2(s[2 * kk + 1][2] - __half2float(__low2half(c3u.h2)),
                                s[2 * kk + 1][3] - __half2float(__high2half(c3u.h2)));
            }
            uint32_t bvh[4][4], bvl[4][4];
#pragma unroll
            for (int np = 0; np < 4; np++) {
                const uint32_t off = (uint32_t)(kk * 16 + trow) * (FST * 2)
                                   + (uint32_t)(np * 16 + tcol) * 2;
                ldmat4t(bvh[np], sVh + off);
                ldmat4t(bvl[np], sVl + off);
            }
#pragma unroll
            for (int np = 0; np < 4; np++) {
                mma_fp(o[np * 2],     aH, &bvh[np][0]);
                mma_fp(o[np * 2 + 1], aH, &bvh[np][2]);
            }
#pragma unroll
            for (int np = 0; np < 4; np++) {
                mma_fp(o[np * 2],     aL, &bvh[np][0]);
                mma_fp(o[np * 2 + 1], aL, &bvh[np][2]);
            }
#pragma unroll
            for (int np = 0; np < 4; np++) {
                mma_fp(o[np * 2],     aH, &bvl[np][0]);
                mma_fp(o[np * 2 + 1], aH, &bvl[np][2]);
            }
        }

        __syncthreads();
        if (jt + 2 < nkt)
            load_kv(stg, (jt + 2) * FBK, tid, gKh, gKl, gVh, gVl);
    }

    // ---- epilogue: normalize, split-bf16, write g_Ah/g_Al ----
    const float inv0 = 1.f / l0, inv1 = 1.f / l1;
#pragma unroll
    for (int nb = 0; nb < 8; nb++) {
        const int d0 = h * D_HEAD + nb * 8 + (lane & 3) * 2;
#pragma unroll
        for (int half_m = 0; half_m < 2; half_m++) {
            const int row = half_m ? row1 : row0;
            const float inv = half_m ? inv1 : inv0;
            const float v0 = o[nb][half_m * 2] * inv;
            const float v1 = o[nb][half_m * 2 + 1] * inv;
            __nv_bfloat16 h0 = __float2bfloat16_rn(v0), h1 = __float2bfloat16_rn(v1);
            __nv_bfloat16 lo0 = __float2bfloat16_rn(v0 - __bfloat162float(h0));
            __nv_bfloat16 lo1 = __float2bfloat16_rn(v1 - __bfloat162float(h1));
            const size_t e = (size_t)(b * SEQ + row) * D_MODEL + d0;
            uint32_t uh = ((uint32_t)__bfloat16_as_ushort(h1) << 16) | __bfloat16_as_ushort(h0);
            uint32_t ul = ((uint32_t)__bfloat16_as_ushort(lo1) << 16) | __bfloat16_as_ushort(lo0);
            *(uint32_t*)(g_Ah + e) = uh;
            *(uint32_t*)(g_Al + e) = ul;
        }
    }
}

// ---------------- launch ----------------
extern "C" void kernel_launch(void* const* d_in, const int* in_sizes, int n_in,
                              void* d_out, int out_size)
{
    const float* x  = (const float*)d_in[0];
    const float* Wq = (const float*)d_in[1];
    const float* bq = (const float*)d_in[2];
    const float* Wk = (const float*)d_in[3];
    const float* bk = (const float*)d_in[4];
    const float* Wv = (const float*)d_in[5];
    const float* bv = (const float*)d_in[6];
    const float* Wo = (const float*)d_in[7];
    float* out = (float*)d_out;

    const int gemmSmem = 2 * BUFB;   // 81920
    cudaFuncSetAttribute(gemm_mma, cudaFuncAttributeMaxDynamicSharedMemorySize, gemmSmem);
    const int flashSmem = (2 * QTILE + 8 * KTILE) * (int)sizeof(__half);   // 110592
    cudaFuncSetAttribute(flash_mma, cudaFuncAttributeMaxDynamicSharedMemorySize, flashSmem);

    cvt_rm<<<M_ROWS * D_MODEL / 4 / 256, 256>>>(x);
    cvt_wt<<<dim3(D_MODEL / 32, D_MODEL / 32, 4), 256>>>(Wq, Wk, Wv, Wo);
    gemm_mma<<<dim3(D_MODEL / 128, M_ROWS / 128, 3), 256, gemmSmem>>>(bq, bk, bv, nullptr, 0);
    flash_mma<<<dim3(SEQ / 128, N_HEADS, BATCH), 256, flashSmem>>>();
    gemm_mma<<<dim3(D_MODEL / 128, M_ROWS / 128, 1), 256, gemmSmem>>>(nullptr, nullptr, nullptr, out, 1);
}

// round 8
// speedup vs baseline: 1.1409x; 1.1409x over previous
#include <cuda_runtime.h>
#include <cuda_bf16.h>
#include <cuda_fp16.h>
#include <cstdint>

#define D_MODEL 1024
#define N_HEADS 16
#define D_HEAD  64
#define BATCH   2
#define SEQ     2048
#define M_ROWS  (BATCH * SEQ)      // 4096

// Q pre-scale: 1/sqrt(Dh) * log2(e)  (softmax computed in exp2 domain)
#define QSCALE 0.1803368801111204f

// ---------------- scratch (no allocations allowed) ----------------
__device__ __half g_Qh[(size_t)BATCH * N_HEADS * SEQ * D_HEAD];
__device__ __half g_Ql[(size_t)BATCH * N_HEADS * SEQ * D_HEAD];
__device__ __half g_Kh[(size_t)BATCH * N_HEADS * SEQ * D_HEAD];
__device__ __half g_Kl[(size_t)BATCH * N_HEADS * SEQ * D_HEAD];
__device__ __half g_Vh[(size_t)BATCH * N_HEADS * SEQ * D_HEAD];   // single fp16 V

__device__ __nv_bfloat16 g_xh[(size_t)M_ROWS * D_MODEL];
__device__ __nv_bfloat16 g_xl[(size_t)M_ROWS * D_MODEL];
__device__ __nv_bfloat16 g_Ah[(size_t)M_ROWS * D_MODEL];
__device__ __nv_bfloat16 g_Al[(size_t)M_ROWS * D_MODEL];
__device__ __nv_bfloat16 g_Wth[(size_t)4 * D_MODEL * D_MODEL];  // W^T hi, [4][n][k]
__device__ __nv_bfloat16 g_Wtl[(size_t)4 * D_MODEL * D_MODEL];  // W^T lo

// ---------------- helpers ----------------
__device__ __forceinline__ uint32_t smem_u32(const void* p) {
    uint32_t a;
    asm("{ .reg .u64 t; cvta.to.shared.u64 t, %1; cvt.u32.u64 %0, t; }" : "=r"(a) : "l"(p));
    return a;
}
__device__ __forceinline__ void cp_async16(uint32_t sa, const void* g) {
    asm volatile("cp.async.cg.shared.global [%0], [%1], 16;\n" :: "r"(sa), "l"(g));
}
__device__ __forceinline__ void ldmat4(uint32_t* r, uint32_t addr) {
    asm volatile("ldmatrix.sync.aligned.m8n8.x4.shared.b16 {%0,%1,%2,%3}, [%4];"
        : "=r"(r[0]), "=r"(r[1]), "=r"(r[2]), "=r"(r[3]) : "r"(addr));
}
__device__ __forceinline__ void ldmat4t(uint32_t* r, uint32_t addr) {
    asm volatile("ldmatrix.sync.aligned.m8n8.x4.trans.shared.b16 {%0,%1,%2,%3}, [%4];"
        : "=r"(r[0]), "=r"(r[1]), "=r"(r[2]), "=r"(r[3]) : "r"(addr));
}
__device__ __forceinline__ void mma_bf(float* c, const uint32_t* a, const uint32_t* b) {
    asm volatile("mma.sync.aligned.m16n8k16.row.col.f32.bf16.bf16.f32 "
        "{%0,%1,%2,%3}, {%4,%5,%6,%7}, {%8,%9}, {%0,%1,%2,%3};"
        : "+f"(c[0]), "+f"(c[1]), "+f"(c[2]), "+f"(c[3])
        : "r"(a[0]), "r"(a[1]), "r"(a[2]), "r"(a[3]), "r"(b[0]), "r"(b[1]));
}
__device__ __forceinline__ void mma_fp(float* c, const uint32_t* a, const uint32_t* b) {
    asm volatile("mma.sync.aligned.m16n8k16.row.col.f32.f16.f16.f32 "
        "{%0,%1,%2,%3}, {%4,%5,%6,%7}, {%8,%9}, {%0,%1,%2,%3};"
        : "+f"(c[0]), "+f"(c[1]), "+f"(c[2]), "+f"(c[3])
        : "r"(a[0]), "r"(a[1]), "r"(a[2]), "r"(a[3]), "r"(b[0]), "r"(b[1]));
}
__device__ __forceinline__ float fexp2(float x) {
    float r; asm("ex2.approx.f32 %0, %1;" : "=f"(r) : "f"(x)); return r;
}
__device__ __forceinline__ uint32_t pack_h2(float a, float b) {
    __half2 h = __halves2half2(__float2half_rn(a), __float2half_rn(b));
    union { __half2 h2; uint32_t u; } c; c.h2 = h; return c.u;
}

// ---------------- conversion kernels ----------------
__global__ __launch_bounds__(256) void cvt_rm(const float* __restrict__ src)
{
    const size_t i4 = (size_t)blockIdx.x * blockDim.x + threadIdx.x;
    if (i4 < (size_t)M_ROWS * D_MODEL / 4) {
        float4 v = ((const float4*)src)[i4];
        float vv[4] = {v.x, v.y, v.z, v.w};
#pragma unroll
        for (int j = 0; j < 4; j++) {
            __nv_bfloat16 h = __float2bfloat16_rn(vv[j]);
            g_xh[i4 * 4 + j] = h;
            g_xl[i4 * 4 + j] = __float2bfloat16_rn(vv[j] - __bfloat162float(h));
        }
    }
}

__global__ __launch_bounds__(256) void cvt_wt(const float* __restrict__ Wq,
                                              const float* __restrict__ Wk,
                                              const float* __restrict__ Wv,
                                              const float* __restrict__ Wo)
{
    __shared__ float t[32][33];
    const int z = blockIdx.z;
    const float* W = (z == 0) ? Wq : (z == 1) ? Wk : (z == 2) ? Wv : Wo;
    __nv_bfloat16* hi = g_Wth + (size_t)z * D_MODEL * D_MODEL;
    __nv_bfloat16* lo = g_Wtl + (size_t)z * D_MODEL * D_MODEL;
    const int n0 = blockIdx.x * 32, k0 = blockIdx.y * 32;
    const int tx = threadIdx.x & 31, ty = threadIdx.x >> 5;
    for (int r = ty; r < 32; r += 8)
        t[r][tx] = W[(size_t)(k0 + r) * D_MODEL + n0 + tx];
    __syncthreads();
    for (int r = ty; r < 32; r += 8) {
        float v = t[tx][r];
        __nv_bfloat16 h = __float2bfloat16_rn(v);
        const size_t o = (size_t)(n0 + r) * D_MODEL + k0 + tx;
        hi[o] = h;
        lo[o] = __float2bfloat16_rn(v - __bfloat162float(h));
    }
}

// ---------------- shared GEMM constants ----------------
#define AST   40
#define TILEB (128 * AST * 2)          // 10240 B per 128x32 bf16 tile
#define KC    32
#define NKC   (D_MODEL / KC)           // 32 chunks

// ---------------- fused QKV GEMM: A loaded once, 3 weights applied ----------------
// stage layout: [Ah, Al, BQh, BQl, BKh, BKl, BVh, BVl] x TILEB
#define QSTAGE (8 * TILEB)             // 81920 B

__device__ __forceinline__ void load_chunk_qkv(uint32_t bufbase, int c, int tid,
        const __nv_bfloat16* const* gs)
{
#pragma unroll
    for (int i = 0; i < 16; i++) {
        const int idx = i * 256 + tid;
        const int t = idx >> 9;            // constant per i
        const int rem = idx & 511;
        const int row = rem >> 2;
        const int seg = rem & 3;
        cp_async16(bufbase + t * TILEB + row * (AST * 2) + seg * 16,
                   gs[t] + (size_t)row * D_MODEL + c * KC + seg * 8);
    }
    asm volatile("cp.async.commit_group;\n" ::: "memory");
}

__global__ __launch_bounds__(256, 1) void gemm_qkv(
        const float* __restrict__ bq, const float* __restrict__ bk,
        const float* __restrict__ bv)
{
    extern __shared__ char smem[];
    const uint32_t sb = smem_u32(smem);
    const int tid = threadIdx.x;
    const int wid = tid >> 5, lane = tid & 31;
    const int wy = wid & 3, wx = wid >> 2;
    const int rowBase = blockIdx.y * 128;
    const int colBase = blockIdx.x * 128;

    const __nv_bfloat16* gs[8];
    gs[0] = g_xh + (size_t)rowBase * D_MODEL;
    gs[1] = g_xl + (size_t)rowBase * D_MODEL;
#pragma unroll
    for (int z = 0; z < 3; z++) {
        gs[2 + 2 * z] = g_Wth + (size_t)z * D_MODEL * D_MODEL + (size_t)colBase * D_MODEL;
        gs[3 + 2 * z] = g_Wtl + (size_t)z * D_MODEL * D_MODEL + (size_t)colBase * D_MODEL;
    }

    const uint32_t buf0 = sb, buf1 = sb + QSTAGE;

    float acc[3][2][8][4];
#pragma unroll
    for (int z = 0; z < 3; z++)
#pragma unroll
        for (int mt = 0; mt < 2; mt++)
#pragma unroll
            for (int nt = 0; nt < 8; nt++)
#pragma unroll
                for (int j = 0; j < 4; j++) acc[z][mt][nt][j] = 0.f;

    load_chunk_qkv(buf0, 0, tid, gs);
    load_chunk_qkv(buf1, 1, tid, gs);

    const int arow = (lane & 7) + ((lane >> 3) & 1) * 8;
    const int acol = (lane >> 4) * 8;
    const int brow = (lane & 7) + (lane >> 4) * 8;
    const int bcol = ((lane >> 3) & 1) * 8;

    for (int c = 0; c < NKC; c++) {
        const int b = c & 1;
        if (c < NKC - 1) asm volatile("cp.async.wait_group 1;\n" ::: "memory");
        else             asm volatile("cp.async.wait_group 0;\n" ::: "memory");
        __syncthreads();

        const uint32_t base = b ? buf1 : buf0;

#pragma unroll
        for (int ks = 0; ks < 2; ks++) {
            uint32_t ah[2][4], al[2][4];
#pragma unroll
            for (int mt = 0; mt < 2; mt++) {
                const uint32_t off = (uint32_t)(wy * 32 + mt * 16 + arow) * (AST * 2)
                                   + (uint32_t)(ks * 16 + acol) * 2;
                ldmat4(ah[mt], base + off);
                ldmat4(al[mt], base + TILEB + off);
            }
#pragma unroll
            for (int z = 0; z < 3; z++) {
                uint32_t bh[4][4], bl[4][4];
#pragma unroll
                for (int np = 0; np < 4; np++) {
                    const uint32_t off = (uint32_t)(wx * 64 + np * 16 + brow) * (AST * 2)
                                       + (uint32_t)(ks * 16 + bcol) * 2;
                    ldmat4(bh[np], base + (2 + 2 * z) * TILEB + off);
                    ldmat4(bl[np], base + (3 + 2 * z) * TILEB + off);
                }
#pragma unroll
                for (int mt = 0; mt < 2; mt++)
#pragma unroll
                    for (int np = 0; np < 4; np++) {
                        mma_bf(acc[z][mt][np * 2],     ah[mt], &bh[np][0]);
                        mma_bf(acc[z][mt][np * 2 + 1], ah[mt], &bh[np][2]);
                    }
#pragma unroll
                for (int mt = 0; mt < 2; mt++)
#pragma unroll
                    for (int np = 0; np < 4; np++) {
                        mma_bf(acc[z][mt][np * 2],     ah[mt], &bl[np][0]);
                        mma_bf(acc[z][mt][np * 2 + 1], ah[mt], &bl[np][2]);
                    }
#pragma unroll
                for (int mt = 0; mt < 2; mt++)
#pragma unroll
                    for (int np = 0; np < 4; np++) {
                        mma_bf(acc[z][mt][np * 2],     al[mt], &bh[np][0]);
                        mma_bf(acc[z][mt][np * 2 + 1], al[mt], &bh[np][2]);
                    }
            }
        }
        __syncthreads();
        if (c + 2 < NKC)
            load_chunk_qkv(b ? buf1 : buf0, c + 2, tid, gs);
    }

    // ---------------- epilogue: split-fp16 Q/K, single-fp16 V ----------------
#pragma unroll
    for (int z = 0; z < 3; z++) {
        const float* bias = (z == 0) ? bq : (z == 1) ? bk : bv;
        __half* dH = (z == 0) ? g_Qh : (z == 1) ? g_Kh : g_Vh;
        __half* dL = (z == 0) ? g_Ql : g_Kl;     // unused for z==2
        const float sc = (z == 0) ? QSCALE : 1.0f;
#pragma unroll
        for (int mt = 0; mt < 2; mt++) {
#pragma unroll
            for (int nt = 0; nt < 8; nt++) {
                const int col0 = colBase + wx * 64 + nt * 8 + (lane & 3) * 2;
                const int hh = col0 >> 6, d0 = col0 & (D_HEAD - 1);
                const float b0 = bias[col0], b1 = bias[col0 + 1];
#pragma unroll
                for (int half_m = 0; half_m < 2; half_m++) {
                    const int row = rowBase + wy * 32 + mt * 16 + (lane >> 2) + half_m * 8;
                    const int bb = row >> 11, s = row & (SEQ - 1);
                    float v0 = (acc[z][mt][nt][half_m * 2]     + b0) * sc;
                    float v1 = (acc[z][mt][nt][half_m * 2 + 1] + b1) * sc;
                    __half h0 = __float2half_rn(v0), h1 = __float2half_rn(v1);
                    const size_t e = (((size_t)(bb * N_HEADS + hh)) * SEQ + s) * D_HEAD + d0;
                    *(__half2*)(dH + e) = __halves2half2(h0, h1);
                    if (z < 2) {
                        __half l0 = __float2half_rn(v0 - __half2float(h0));
                        __half l1 = __float2half_rn(v1 - __half2float(h1));
                        *(__half2*)(dL + e) = __halves2half2(l0, l1);
                    }
                }
            }
        }
    }
}

// ---------------- Wo GEMM (split-bf16, out = A @ Wo^T_stored) ----------------
#define BUFB  (4 * TILEB)

__device__ __forceinline__ void load_chunk_wo(uint32_t bufbase, int c, int tid,
        const __nv_bfloat16* g0, const __nv_bfloat16* g1,
        const __nv_bfloat16* g2, const __nv_bfloat16* g3)
{
    const __nv_bfloat16* gs[4] = {g0, g1, g2, g3};
#pragma unroll
    for (int i = 0; i < 8; i++) {
        const int idx = i * 256 + tid;
        const int t = idx >> 9;
        const int rem = idx & 511;
        const int row = rem >> 2;
        const int seg = rem & 3;
        cp_async16(bufbase + t * TILEB + row * (AST * 2) + seg * 16,
                   gs[t] + (size_t)row * D_MODEL + c * KC + seg * 8);
    }
    asm volatile("cp.async.commit_group;\n" ::: "memory");
}

__global__ __launch_bounds__(256, 1) void gemm_wo(float* __restrict__ out)
{
    extern __shared__ char smem[];
    const uint32_t sb = smem_u32(smem);
    const int tid = threadIdx.x;
    const int wid = tid >> 5, lane = tid & 31;
    const int wy = wid & 3, wx = wid >> 2;
    const int rowBase = blockIdx.y * 128;
    const int colBase = blockIdx.x * 128;

    const __nv_bfloat16* Ah = g_Ah + (size_t)rowBase * D_MODEL;
    const __nv_bfloat16* Al = g_Al + (size_t)rowBase * D_MODEL;
    const __nv_bfloat16* Bh = g_Wth + (size_t)3 * D_MODEL * D_MODEL + (size_t)colBase * D_MODEL;
    const __nv_bfloat16* Bl = g_Wtl + (size_t)3 * D_MODEL * D_MODEL + (size_t)colBase * D_MODEL;

    const uint32_t buf0 = sb, buf1 = sb + BUFB;

    float acc[2][8][4];
#pragma unroll
    for (int mt = 0; mt < 2; mt++)
#pragma unroll
        for (int nt = 0; nt < 8; nt++)
#pragma unroll
            for (int j = 0; j < 4; j++) acc[mt][nt][j] = 0.f;

    load_chunk_wo(buf0, 0, tid, Ah, Al, Bh, Bl);
    load_chunk_wo(buf1, 1, tid, Ah, Al, Bh, Bl);

    const int arow = (lane & 7) + ((lane >> 3) & 1) * 8;
    const int acol = (lane >> 4) * 8;
    const int brow = (lane & 7) + (lane >> 4) * 8;
    const int bcol = ((lane >> 3) & 1) * 8;

    for (int c = 0; c < NKC; c++) {
        const int b = c & 1;
        if (c < NKC - 1) asm volatile("cp.async.wait_group 1;\n" ::: "memory");
        else             asm volatile("cp.async.wait_group 0;\n" ::: "memory");
        __syncthreads();

        const uint32_t base = b ? buf1 : buf0;
        const uint32_t aHs = base,             aLs = base + TILEB;
        const uint32_t bHs = base + 2 * TILEB, bLs = base + 3 * TILEB;

#pragma unroll
        for (int ks = 0; ks < 2; ks++) {
            uint32_t ah[2][4], al[2][4], bh[4][4], bl[4][4];
#pragma unroll
            for (int mt = 0; mt < 2; mt++) {
                const uint32_t off = (uint32_t)(wy * 32 + mt * 16 + arow) * (AST * 2)
                                   + (uint32_t)(ks * 16 + acol) * 2;
                ldmat4(ah[mt], aHs + off);
                ldmat4(al[mt], aLs + off);
            }
#pragma unroll
            for (int np = 0; np < 4; np++) {
                const uint32_t off = (uint32_t)(wx * 64 + np * 16 + brow) * (AST * 2)
                                   + (uint32_t)(ks * 16 + bcol) * 2;
                ldmat4(bh[np], bHs + off);
                ldmat4(bl[np], bLs + off);
            }
#pragma unroll
            for (int mt = 0; mt < 2; mt++)
#pragma unroll
                for (int np = 0; np < 4; np++) {
                    mma_bf(acc[mt][np * 2],     ah[mt], &bh[np][0]);
                    mma_bf(acc[mt][np * 2 + 1], ah[mt], &bh[np][2]);
                }
#pragma unroll
            for (int mt = 0; mt < 2; mt++)
#pragma unroll
                for (int np = 0; np < 4; np++) {
                    mma_bf(acc[mt][np * 2],     ah[mt], &bl[np][0]);
                    mma_bf(acc[mt][np * 2 + 1], ah[mt], &bl[np][2]);
                }
#pragma unroll
            for (int mt = 0; mt < 2; mt++)
#pragma unroll
                for (int np = 0; np < 4; np++) {
                    mma_bf(acc[mt][np * 2],     al[mt], &bh[np][0]);
                    mma_bf(acc[mt][np * 2 + 1], al[mt], &bh[np][2]);
                }
        }
        __syncthreads();
        if (c + 2 < NKC)
            load_chunk_wo(b ? buf1 : buf0, c + 2, tid, Ah, Al, Bh, Bl);
    }

#pragma unroll
    for (int mt = 0; mt < 2; mt++)
#pragma unroll
        for (int nt = 0; nt < 8; nt++)
#pragma unroll
            for (int j = 0; j < 4; j++) {
                const int row = rowBase + wy * 32 + mt * 16 + (lane >> 2) + (j >> 1) * 8;
                const int col = colBase + wx * 64 + nt * 8 + (lane & 3) * 2 + (j & 1);
                out[(size_t)row * D_MODEL + col] = acc[mt][nt][j];
            }
}

// ---------------- tensor-core flash attention ----------------
// CTA: 256 thr / 8 warps; BQ=128 (16 rows per warp), BK=64.
// S = qh*kh + ql*kh + qh*kl ; PV = ph*v + pl*v (V single fp16)
#define FBK    64
#define FST    72
#define QTILE  (128 * FST)             // halves
#define KTILE  (64 * FST)              // halves
#define KVSTG  (3 * KTILE)             // Kh, Kl, Vh

__device__ __forceinline__ void load_kv(__half* stagep, int kb, int tid,
        const __half* gKh, const __half* gKl, const __half* gV)
{
#pragma unroll
    for (int i = 0; i < 6; i++) {
        const int idx = i * 256 + tid;
        const int t = idx >> 9;            // constant per i
        const int rem = idx & 511;
        const int row = rem >> 3;
        const int seg = rem & 7;
        const __half* g = (t == 0 ? gKh : t == 1 ? gKl : gV)
                        + (size_t)(kb + row) * D_HEAD + seg * 8;
        cp_async16(smem_u32(stagep + t * KTILE + row * FST + seg * 8), g);
    }
    asm volatile("cp.async.commit_group;\n" ::: "memory");
}

__global__ __launch_bounds__(256, 1) void flash_mma()
{
    extern __shared__ __half fsm[];
    const int tid = threadIdx.x;
    const int wid = tid >> 5, lane = tid & 31;
    const int qt = blockIdx.x, h = blockIdx.y, b = blockIdx.z;
    const int bh = b * N_HEADS + h;
    const int qBase = qt * 128;
    const size_t gbase = (size_t)bh * SEQ * D_HEAD;

    const __half* gQh = g_Qh + gbase;
    const __half* gQl = g_Ql + gbase;
    const __half* gKh = g_Kh + gbase;
    const __half* gKl = g_Kl + gbase;
    const __half* gV  = g_Vh + gbase;

    __half* sQh = fsm;
    __half* sQl = fsm + QTILE;
    __half* stage0 = fsm + 2 * QTILE;
    __half* stage1 = stage0 + KVSTG;

    // Q tile load (group 0)
#pragma unroll
    for (int i = 0; i < 8; i++) {
        const int idx = i * 256 + tid;
        const int t = idx >> 10;
        const int rem = idx & 1023;
        const int row = rem >> 3;
        const int seg = rem & 7;
        const __half* g = (t ? gQl : gQh) + (size_t)(qBase + row) * D_HEAD + seg * 8;
        cp_async16(smem_u32((t ? sQl : sQh) + row * FST + seg * 8), g);
    }
    asm volatile("cp.async.commit_group;\n" ::: "memory");

    const int nkt = 2 * (qt + 1);
    load_kv(stage0, 0, tid, gKh, gKl, gV);
    load_kv(stage1, FBK, tid, gKh, gKl, gV);

    const int arow = (lane & 7) + ((lane >> 3) & 1) * 8;
    const int acol = (lane >> 4) * 8;
    const int brow = (lane & 7) + (lane >> 4) * 8;
    const int bcol = ((lane >> 3) & 1) * 8;
    const int trow = (lane & 7) + ((lane >> 3) & 1) * 8;
    const int tcol = (lane >> 4) * 8;

    uint32_t qh[4][4], ql[4][4];
    float o[8][4];
#pragma unroll
    for (int nb = 0; nb < 8; nb++)
#pragma unroll
        for (int j = 0; j < 4; j++) o[nb][j] = 0.f;
    float m0 = -1e30f, m1 = -1e30f, l0 = 0.f, l1 = 0.f;

    const int row0 = qBase + wid * 16 + (lane >> 2);
    const int row1 = row0 + 8;

    for (int jt = 0; jt < nkt; jt++) {
        __half* stg = (jt & 1) ? stage1 : stage0;
        if (jt < nkt - 1) asm volatile("cp.async.wait_group 1;\n" ::: "memory");
        else              asm volatile("cp.async.wait_group 0;\n" ::: "memory");
        __syncthreads();

        if (jt == 0) {
#pragma unroll
            for (int kk = 0; kk < 4; kk++) {
                const uint32_t off = (uint32_t)(wid * 16 + arow) * (FST * 2)
                                   + (uint32_t)(kk * 16 + acol) * 2;
                ldmat4(qh[kk], smem_u32(sQh) + off);
                ldmat4(ql[kk], smem_u32(sQl) + off);
            }
        }

        const uint32_t sKh = smem_u32(stg);
        const uint32_t sKl = sKh + KTILE * 2;
        const uint32_t sV  = sKh + 2 * KTILE * 2;

        float s[8][4];
#pragma unroll
        for (int nb = 0; nb < 8; nb++)
#pragma unroll
            for (int j = 0; j < 4; j++) s[nb][j] = 0.f;

        // ---- S = Q K^T : pass-major ----
#pragma unroll
        for (int kk = 0; kk < 4; kk++) {
            uint32_t bkh[4][4], bkl[4][4];
#pragma unroll
            for (int np = 0; np < 4; np++) {
                const uint32_t off = (uint32_t)(np * 16 + brow) * (FST * 2)
                                   + (uint32_t)(kk * 16 + bcol) * 2;
                ldmat4(bkh[np], sKh + off);
                ldmat4(bkl[np], sKl + off);
            }
#pragma unroll
            for (int np = 0; np < 4; np++) {
                mma_fp(s[np * 2],     qh[kk], &bkh[np][0]);
                mma_fp(s[np * 2 + 1], qh[kk], &bkh[np][2]);
            }
#pragma unroll
            for (int np = 0; np < 4; np++) {
                mma_fp(s[np * 2],     ql[kk], &bkh[np][0]);
                mma_fp(s[np * 2 + 1], ql[kk], &bkh[np][2]);
            }
#pragma unroll
            for (int np = 0; np < 4; np++) {
                mma_fp(s[np * 2],     qh[kk], &bkl[np][0]);
                mma_fp(s[np * 2 + 1], qh[kk], &bkl[np][2]);
            }
        }

        // ---- causal mask (partial tiles only) ----
        if (jt >= 2 * qt) {
            const int kb = jt * FBK;
#pragma unroll
            for (int nb = 0; nb < 8; nb++) {
#pragma unroll
                for (int j = 0; j < 4; j++) {
                    const int key = kb + nb * 8 + (lane & 3) * 2 + (j & 1);
                    const int qr = (j < 2) ? row0 : row1;
                    if (key > qr) s[nb][j] = -1e30f;
                }
            }
        }

        // ---- online softmax (exp2 domain) ----
        float mx0 = -1e30f, mx1 = -1e30f;
#pragma unroll
        for (int nb = 0; nb < 8; nb++) {
            mx0 = fmaxf(mx0, fmaxf(s[nb][0], s[nb][1]));
            mx1 = fmaxf(mx1, fmaxf(s[nb][2], s[nb][3]));
        }
        mx0 = fmaxf(mx0, __shfl_xor_sync(0xffffffffu, mx0, 1));
        mx0 = fmaxf(mx0, __shfl_xor_sync(0xffffffffu, mx0, 2));
        mx1 = fmaxf(mx1, __shfl_xor_sync(0xffffffffu, mx1, 1));
        mx1 = fmaxf(mx1, __shfl_xor_sync(0xffffffffu, mx1, 2));
        const float mn0 = fmaxf(m0, mx0), mn1 = fmaxf(m1, mx1);
        const float c0 = fexp2(m0 - mn0), c1 = fexp2(m1 - mn1);
        m0 = mn0; m1 = mn1;

        float sum0 = 0.f, sum1 = 0.f;
#pragma unroll
        for (int nb = 0; nb < 8; nb++) {
            s[nb][0] = fexp2(s[nb][0] - m0); sum0 += s[nb][0];
            s[nb][1] = fexp2(s[nb][1] - m0); sum0 += s[nb][1];
            s[nb][2] = fexp2(s[nb][2] - m1); sum1 += s[nb][2];
            s[nb][3] = fexp2(s[nb][3] - m1); sum1 += s[nb][3];
        }
        sum0 += __shfl_xor_sync(0xffffffffu, sum0, 1);
        sum0 += __shfl_xor_sync(0xffffffffu, sum0, 2);
        sum1 += __shfl_xor_sync(0xffffffffu, sum1, 1);
        sum1 += __shfl_xor_sync(0xffffffffu, sum1, 2);
        l0 = l0 * c0 + sum0;
        l1 = l1 * c1 + sum1;

#pragma unroll
        for (int nb = 0; nb < 8; nb++) {
            o[nb][0] *= c0; o[nb][1] *= c0;
            o[nb][2] *= c1; o[nb][3] *= c1;
        }

        // ---- O += P V : P split (hi+lo), V single ----
#pragma unroll
        for (int kk = 0; kk < 4; kk++) {
            uint32_t aH[4], aL[4];
            aH[0] = pack_h2(s[2 * kk][0], s[2 * kk][1]);
            aH[1] = pack_h2(s[2 * kk][2], s[2 * kk][3]);
            aH[2] = pack_h2(s[2 * kk + 1][0], s[2 * kk + 1][1]);
            aH[3] = pack_h2(s[2 * kk + 1][2], s[2 * kk + 1][3]);
            {
                union { uint32_t u; __half2 h2; } c0u, c1u, c2u, c3u;
                c0u.u = aH[0]; c1u.u = aH[1]; c2u.u = aH[2]; c3u.u = aH[3];
                aL[0] = pack_h2(s[2 * kk][0] - __half2float(__low2half(c0u.h2)),
                                s[2 * kk][1] - __half2float(__high2half(c0u.h2)));
                aL[1] = pack_h2(s[2 * kk][2] - __half2float(__low2half(c1u.h2)),
                                s[2 * kk][3] - __half2float(__high2half(c1u.h2)));
                aL[2] = pack_h2(s[2 * kk + 1][0] - __half2float(__low2half(c2u.h2)),
                                s[2 * kk + 1][1] - __half2float(__high2half(c2u.h2)));
                aL[3] = pack_h2(s[2 * kk + 1][2] - __half2float(__low2half(c3u.h2)),
                                s[2 * kk + 1][3] - __half2float(__high2half(c3u.h2)));
            }
            uint32_t bv[4][4];
#pragma unroll
            for (int np = 0; np < 4; np++) {
                const uint32_t off = (uint32_t)(kk * 16 + trow) * (FST * 2)
                                   + (uint32_t)(np * 16 + tcol) * 2;
                ldmat4t(bv[np], sV + off);
            }
#pragma unroll
            for (int np = 0; np < 4; np++) {
                mma_fp(o[np * 2],     aH, &bv[np][0]);
                mma_fp(o[np * 2 + 1], aH, &bv[np][2]);
            }
#pragma unroll
            for (int np = 0; np < 4; np++) {
                mma_fp(o[np * 2],     aL, &bv[np][0]);
                mma_fp(o[np * 2 + 1], aL, &bv[np][2]);
            }
        }

        __syncthreads();
        if (jt + 2 < nkt)
            load_kv(stg, (jt + 2) * FBK, tid, gKh, gKl, gV);
    }

    // ---- epilogue: normalize, split-bf16, write g_Ah/g_Al ----
    const float inv0 = 1.f / l0, inv1 = 1.f / l1;
#pragma unroll
    for (int nb = 0; nb < 8; nb++) {
        const int d0 = h * D_HEAD + nb * 8 + (lane & 3) * 2;
#pragma unroll
        for (int half_m = 0; half_m < 2; half_m++) {
            const int row = half_m ? row1 : row0;
            const float inv = half_m ? inv1 : inv0;
            const float v0 = o[nb][half_m * 2] * inv;
            const float v1 = o[nb][half_m * 2 + 1] * inv;
            __nv_bfloat16 h0 = __float2bfloat16_rn(v0), h1 = __float2bfloat16_rn(v1);
            __nv_bfloat16 lo0 = __float2bfloat16_rn(v0 - __bfloat162float(h0));
            __nv_bfloat16 lo1 = __float2bfloat16_rn(v1 - __bfloat162float(h1));
            const size_t e = (size_t)(b * SEQ + row) * D_MODEL + d0;
            uint32_t uh = ((uint32_t)__bfloat16_as_ushort(h1) << 16) | __bfloat16_as_ushort(h0);
            uint32_t ul = ((uint32_t)__bfloat16_as_ushort(lo1) << 16) | __bfloat16_as_ushort(lo0);
            *(uint32_t*)(g_Ah + e) = uh;
            *(uint32_t*)(g_Al + e) = ul;
        }
    }
}

// ---------------- launch ----------------
extern "C" void kernel_launch(void* const* d_in, const int* in_sizes, int n_in,
                              void* d_out, int out_size)
{
    const float* x  = (const float*)d_in[0];
    const float* Wq = (const float*)d_in[1];
    const float* bq = (const float*)d_in[2];
    const float* Wk = (const float*)d_in[3];
    const float* bk = (const float*)d_in[4];
    const float* Wv = (const float*)d_in[5];
    const float* bv = (const float*)d_in[6];
    const float* Wo = (const float*)d_in[7];
    float* out = (float*)d_out;

    const int qkvSmem = 2 * QSTAGE;                                   // 163840
    cudaFuncSetAttribute(gemm_qkv, cudaFuncAttributeMaxDynamicSharedMemorySize, qkvSmem);
    const int woSmem = 2 * BUFB;                                      // 81920
    cudaFuncSetAttribute(gemm_wo, cudaFuncAttributeMaxDynamicSharedMemorySize, woSmem);
    const int flashSmem = (2 * QTILE + 2 * KVSTG) * (int)sizeof(__half);  // 92160
    cudaFuncSetAttribute(flash_mma, cudaFuncAttributeMaxDynamicSharedMemorySize, flashSmem);

    cvt_rm<<<M_ROWS * D_MODEL / 4 / 256, 256>>>(x);
    cvt_wt<<<dim3(D_MODEL / 32, D_MODEL / 32, 4), 256>>>(Wq, Wk, Wv, Wo);
    gemm_qkv<<<dim3(D_MODEL / 128, M_ROWS / 128), 256, qkvSmem>>>(bq, bk, bv);
    flash_mma<<<dim3(SEQ / 128, N_HEADS, BATCH), 256, flashSmem>>>();
    gemm_wo<<<dim3(D_MODEL / 128, M_ROWS / 128), 256, woSmem>>>(out);
}

// round 9
// speedup vs baseline: 1.2103x; 1.0608x over previous
#include <cuda_runtime.h>
#include <cuda_bf16.h>
#include <cuda_fp16.h>
#include <cstdint>

#define D_MODEL 1024
#define N_HEADS 16
#define D_HEAD  64
#define BATCH   2
#define SEQ     2048
#define M_ROWS  (BATCH * SEQ)      // 4096

// Q pre-scale: 1/sqrt(Dh) * log2(e)  (softmax computed in exp2 domain)
#define QSCALE 0.1803368801111204f

// ---------------- scratch (no allocations allowed) ----------------
__device__ __half g_Qh[(size_t)BATCH * N_HEADS * SEQ * D_HEAD];
__device__ __half g_Ql[(size_t)BATCH * N_HEADS * SEQ * D_HEAD];
__device__ __half g_Kh[(size_t)BATCH * N_HEADS * SEQ * D_HEAD];
__device__ __half g_Kl[(size_t)BATCH * N_HEADS * SEQ * D_HEAD];
__device__ __half g_Vh[(size_t)BATCH * N_HEADS * SEQ * D_HEAD];   // single fp16 V

__device__ __nv_bfloat16 g_xh[(size_t)M_ROWS * D_MODEL];
__device__ __nv_bfloat16 g_xl[(size_t)M_ROWS * D_MODEL];
__device__ __nv_bfloat16 g_Ah[(size_t)M_ROWS * D_MODEL];
__device__ __nv_bfloat16 g_Al[(size_t)M_ROWS * D_MODEL];
__device__ __nv_bfloat16 g_Wth[(size_t)4 * D_MODEL * D_MODEL];  // W^T hi, [4][n][k]
__device__ __nv_bfloat16 g_Wtl[(size_t)4 * D_MODEL * D_MODEL];  // W^T lo

// ---------------- helpers ----------------
__device__ __forceinline__ uint32_t smem_u32(const void* p) {
    uint32_t a;
    asm("{ .reg .u64 t; cvta.to.shared.u64 t, %1; cvt.u32.u64 %0, t; }" : "=r"(a) : "l"(p));
    return a;
}
__device__ __forceinline__ void cp_async16(uint32_t sa, const void* g) {
    asm volatile("cp.async.cg.shared.global [%0], [%1], 16;\n" :: "r"(sa), "l"(g));
}
__device__ __forceinline__ void ldmat4(uint32_t* r, uint32_t addr) {
    asm volatile("ldmatrix.sync.aligned.m8n8.x4.shared.b16 {%0,%1,%2,%3}, [%4];"
        : "=r"(r[0]), "=r"(r[1]), "=r"(r[2]), "=r"(r[3]) : "r"(addr));
}
__device__ __forceinline__ void ldmat4t(uint32_t* r, uint32_t addr) {
    asm volatile("ldmatrix.sync.aligned.m8n8.x4.trans.shared.b16 {%0,%1,%2,%3}, [%4];"
        : "=r"(r[0]), "=r"(r[1]), "=r"(r[2]), "=r"(r[3]) : "r"(addr));
}
__device__ __forceinline__ void mma_bf(float* c, const uint32_t* a, const uint32_t* b) {
    asm volatile("mma.sync.aligned.m16n8k16.row.col.f32.bf16.bf16.f32 "
        "{%0,%1,%2,%3}, {%4,%5,%6,%7}, {%8,%9}, {%0,%1,%2,%3};"
        : "+f"(c[0]), "+f"(c[1]), "+f"(c[2]), "+f"(c[3])
        : "r"(a[0]), "r"(a[1]), "r"(a[2]), "r"(a[3]), "r"(b[0]), "r"(b[1]));
}
__device__ __forceinline__ void mma_fp(float* c, const uint32_t* a, const uint32_t* b) {
    asm volatile("mma.sync.aligned.m16n8k16.row.col.f32.f16.f16.f32 "
        "{%0,%1,%2,%3}, {%4,%5,%6,%7}, {%8,%9}, {%0,%1,%2,%3};"
        : "+f"(c[0]), "+f"(c[1]), "+f"(c[2]), "+f"(c[3])
        : "r"(a[0]), "r"(a[1]), "r"(a[2]), "r"(a[3]), "r"(b[0]), "r"(b[1]));
}
__device__ __forceinline__ float fexp2(float x) {
    float r; asm("ex2.approx.f32 %0, %1;" : "=f"(r) : "f"(x)); return r;
}
// pack two f32 into f16x2 in ONE instruction: x -> low half, y -> high half
__device__ __forceinline__ uint32_t pack2(float x, float y) {
    uint32_t r; asm("cvt.rn.f16x2.f32 %0, %1, %2;" : "=r"(r) : "f"(y), "f"(x)); return r;
}
__device__ __forceinline__ float2 unpack2(uint32_t u) {
    __half2 h; *reinterpret_cast<uint32_t*>(&h) = u;
    return __half22float2(h);
}

// ---------------- conversion kernels ----------------
__global__ __launch_bounds__(256) void cvt_rm(const float* __restrict__ src)
{
    const size_t i4 = (size_t)blockIdx.x * blockDim.x + threadIdx.x;
    if (i4 < (size_t)M_ROWS * D_MODEL / 4) {
        float4 v = ((const float4*)src)[i4];
        float vv[4] = {v.x, v.y, v.z, v.w};
#pragma unroll
        for (int j = 0; j < 4; j++) {
            __nv_bfloat16 h = __float2bfloat16_rn(vv[j]);
            g_xh[i4 * 4 + j] = h;
            g_xl[i4 * 4 + j] = __float2bfloat16_rn(vv[j] - __bfloat162float(h));
        }
    }
}

__global__ __launch_bounds__(256) void cvt_wt(const float* __restrict__ Wq,
                                              const float* __restrict__ Wk,
                                              const float* __restrict__ Wv,
                                              const float* __restrict__ Wo)
{
    __shared__ float t[32][33];
    const int z = blockIdx.z;
    const float* W = (z == 0) ? Wq : (z == 1) ? Wk : (z == 2) ? Wv : Wo;
    __nv_bfloat16* hi = g_Wth + (size_t)z * D_MODEL * D_MODEL;
    __nv_bfloat16* lo = g_Wtl + (size_t)z * D_MODEL * D_MODEL;
    const int n0 = blockIdx.x * 32, k0 = blockIdx.y * 32;
    const int tx = threadIdx.x & 31, ty = threadIdx.x >> 5;
    for (int r = ty; r < 32; r += 8)
        t[r][tx] = W[(size_t)(k0 + r) * D_MODEL + n0 + tx];
    __syncthreads();
    for (int r = ty; r < 32; r += 8) {
        float v = t[tx][r];
        __nv_bfloat16 h = __float2bfloat16_rn(v);
        const size_t o = (size_t)(n0 + r) * D_MODEL + k0 + tx;
        hi[o] = h;
        lo[o] = __float2bfloat16_rn(v - __bfloat162float(h));
    }
}

// ---------------- shared GEMM constants ----------------
#define AST   40
#define TILEB (128 * AST * 2)          // 10240 B per 128x32 bf16 tile
#define KC    32
#define NKC   (D_MODEL / KC)           // 32 chunks

// ---------------- fused QKV GEMM ----------------
#define QSTAGE (8 * TILEB)             // 81920 B

__device__ __forceinline__ void load_chunk_qkv(uint32_t bufbase, int c, int tid,
        const __nv_bfloat16* const* gs)
{
#pragma unroll
    for (int i = 0; i < 16; i++) {
        const int idx = i * 256 + tid;
        const int t = idx >> 9;
        const int rem = idx & 511;
        const int row = rem >> 2;
        const int seg = rem & 3;
        cp_async16(bufbase + t * TILEB + row * (AST * 2) + seg * 16,
                   gs[t] + (size_t)row * D_MODEL + c * KC + seg * 8);
    }
    asm volatile("cp.async.commit_group;\n" ::: "memory");
}

__global__ __launch_bounds__(256, 1) void gemm_qkv(
        const float* __restrict__ bq, const float* __restrict__ bk,
        const float* __restrict__ bv)
{
    extern __shared__ char smem[];
    const uint32_t sb = smem_u32(smem);
    const int tid = threadIdx.x;
    const int wid = tid >> 5, lane = tid & 31;
    const int wy = wid & 3, wx = wid >> 2;
    const int rowBase = blockIdx.y * 128;
    const int colBase = blockIdx.x * 128;

    const __nv_bfloat16* gs[8];
    gs[0] = g_xh + (size_t)rowBase * D_MODEL;
    gs[1] = g_xl + (size_t)rowBase * D_MODEL;
#pragma unroll
    for (int z = 0; z < 3; z++) {
        gs[2 + 2 * z] = g_Wth + (size_t)z * D_MODEL * D_MODEL + (size_t)colBase * D_MODEL;
        gs[3 + 2 * z] = g_Wtl + (size_t)z * D_MODEL * D_MODEL + (size_t)colBase * D_MODEL;
    }

    const uint32_t buf0 = sb, buf1 = sb + QSTAGE;

    float acc[3][2][8][4];
#pragma unroll
    for (int z = 0; z < 3; z++)
#pragma unroll
        for (int mt = 0; mt < 2; mt++)
#pragma unroll
            for (int nt = 0; nt < 8; nt++)
#pragma unroll
                for (int j = 0; j < 4; j++) acc[z][mt][nt][j] = 0.f;

    load_chunk_qkv(buf0, 0, tid, gs);
    load_chunk_qkv(buf1, 1, tid, gs);

    const int arow = (lane & 7) + ((lane >> 3) & 1) * 8;
    const int acol = (lane >> 4) * 8;
    const int brow = (lane & 7) + (lane >> 4) * 8;
    const int bcol = ((lane >> 3) & 1) * 8;

    for (int c = 0; c < NKC; c++) {
        const int b = c & 1;
        if (c < NKC - 1) asm volatile("cp.async.wait_group 1;\n" ::: "memory");
        else             asm volatile("cp.async.wait_group 0;\n" ::: "memory");
        __syncthreads();

        const uint32_t base = b ? buf1 : buf0;

#pragma unroll
        for (int ks = 0; ks < 2; ks++) {
            uint32_t ah[2][4], al[2][4];
#pragma unroll
            for (int mt = 0; mt < 2; mt++) {
                const uint32_t off = (uint32_t)(wy * 32 + mt * 16 + arow) * (AST * 2)
                                   + (uint32_t)(ks * 16 + acol) * 2;
                ldmat4(ah[mt], base + off);
                ldmat4(al[mt], base + TILEB + off);
            }
#pragma unroll
            for (int z = 0; z < 3; z++) {
#pragma unroll
                for (int np = 0; np < 4; np++) {
                    uint32_t bh[4], bl[4];
                    const uint32_t off = (uint32_t)(wx * 64 + np * 16 + brow) * (AST * 2)
                                       + (uint32_t)(ks * 16 + bcol) * 2;
                    ldmat4(bh, base + (2 + 2 * z) * TILEB + off);
                    ldmat4(bl, base + (3 + 2 * z) * TILEB + off);
#pragma unroll
                    for (int mt = 0; mt < 2; mt++) {
                        mma_bf(acc[z][mt][np * 2],     ah[mt], &bh[0]);
                        mma_bf(acc[z][mt][np * 2 + 1], ah[mt], &bh[2]);
                        mma_bf(acc[z][mt][np * 2],     ah[mt], &bl[0]);
                        mma_bf(acc[z][mt][np * 2 + 1], ah[mt], &bl[2]);
                        mma_bf(acc[z][mt][np * 2],     al[mt], &bh[0]);
                        mma_bf(acc[z][mt][np * 2 + 1], al[mt], &bh[2]);
                    }
                }
            }
        }
        __syncthreads();
        if (c + 2 < NKC)
            load_chunk_qkv(b ? buf1 : buf0, c + 2, tid, gs);
    }

    // epilogue: split-fp16 Q/K, single-fp16 V
#pragma unroll
    for (int z = 0; z < 3; z++) {
        const float* bias = (z == 0) ? bq : (z == 1) ? bk : bv;
        __half* dH = (z == 0) ? g_Qh : (z == 1) ? g_Kh : g_Vh;
        __half* dL = (z == 0) ? g_Ql : g_Kl;
        const float sc = (z == 0) ? QSCALE : 1.0f;
#pragma unroll
        for (int mt = 0; mt < 2; mt++) {
#pragma unroll
            for (int nt = 0; nt < 8; nt++) {
                const int col0 = colBase + wx * 64 + nt * 8 + (lane & 3) * 2;
                const int hh = col0 >> 6, d0 = col0 & (D_HEAD - 1);
                const float b0 = bias[col0], b1 = bias[col0 + 1];
#pragma unroll
                for (int half_m = 0; half_m < 2; half_m++) {
                    const int row = rowBase + wy * 32 + mt * 16 + (lane >> 2) + half_m * 8;
                    const int bb = row >> 11, s = row & (SEQ - 1);
                    float v0 = (acc[z][mt][nt][half_m * 2]     + b0) * sc;
                    float v1 = (acc[z][mt][nt][half_m * 2 + 1] + b1) * sc;
                    const uint32_t hpair = pack2(v0, v1);
                    const size_t e = (((size_t)(bb * N_HEADS + hh)) * SEQ + s) * D_HEAD + d0;
                    *(uint32_t*)(dH + e) = hpair;
                    if (z < 2) {
                        float2 f = unpack2(hpair);
                        *(uint32_t*)(dL + e) = pack2(v0 - f.x, v1 - f.y);
                    }
                }
            }
        }
    }
}

// ---------------- Wo GEMM (2 CTAs/SM) ----------------
#define BUFB  (4 * TILEB)

__device__ __forceinline__ void load_chunk_wo(uint32_t bufbase, int c, int tid,
        const __nv_bfloat16* g0, const __nv_bfloat16* g1,
        const __nv_bfloat16* g2, const __nv_bfloat16* g3)
{
    const __nv_bfloat16* gs[4] = {g0, g1, g2, g3};
#pragma unroll
    for (int i = 0; i < 8; i++) {
        const int idx = i * 256 + tid;
        const int t = idx >> 9;
        const int rem = idx & 511;
        const int row = rem >> 2;
        const int seg = rem & 3;
        cp_async16(bufbase + t * TILEB + row * (AST * 2) + seg * 16,
                   gs[t] + (size_t)row * D_MODEL + c * KC + seg * 8);
    }
    asm volatile("cp.async.commit_group;\n" ::: "memory");
}

__global__ __launch_bounds__(256, 2) void gemm_wo(float* __restrict__ out)
{
    extern __shared__ char smem[];
    const uint32_t sb = smem_u32(smem);
    const int tid = threadIdx.x;
    const int wid = tid >> 5, lane = tid & 31;
    const int wy = wid & 3, wx = wid >> 2;
    const int rowBase = blockIdx.y * 128;
    const int colBase = blockIdx.x * 128;

    const __nv_bfloat16* Ah = g_Ah + (size_t)rowBase * D_MODEL;
    const __nv_bfloat16* Al = g_Al + (size_t)rowBase * D_MODEL;
    const __nv_bfloat16* Bh = g_Wth + (size_t)3 * D_MODEL * D_MODEL + (size_t)colBase * D_MODEL;
    const __nv_bfloat16* Bl = g_Wtl + (size_t)3 * D_MODEL * D_MODEL + (size_t)colBase * D_MODEL;

    const uint32_t buf0 = sb, buf1 = sb + BUFB;

    float acc[2][8][4];
#pragma unroll
    for (int mt = 0; mt < 2; mt++)
#pragma unroll
        for (int nt = 0; nt < 8; nt++)
#pragma unroll
            for (int j = 0; j < 4; j++) acc[mt][nt][j] = 0.f;

    load_chunk_wo(buf0, 0, tid, Ah, Al, Bh, Bl);
    load_chunk_wo(buf1, 1, tid, Ah, Al, Bh, Bl);

    const int arow = (lane & 7) + ((lane >> 3) & 1) * 8;
    const int acol = (lane >> 4) * 8;
    const int brow = (lane & 7) + (lane >> 4) * 8;
    const int bcol = ((lane >> 3) & 1) * 8;

    for (int c = 0; c < NKC; c++) {
        const int b = c & 1;
        if (c < NKC - 1) asm volatile("cp.async.wait_group 1;\n" ::: "memory");
        else             asm volatile("cp.async.wait_group 0;\n" ::: "memory");
        __syncthreads();

        const uint32_t base = b ? buf1 : buf0;
        const uint32_t aHs = base,             aLs = base + TILEB;
        const uint32_t bHs = base + 2 * TILEB, bLs = base + 3 * TILEB;

#pragma unroll
        for (int ks = 0; ks < 2; ks++) {
            uint32_t ah[2][4], al[2][4];
#pragma unroll
            for (int mt = 0; mt < 2; mt++) {
                const uint32_t off = (uint32_t)(wy * 32 + mt * 16 + arow) * (AST * 2)
                                   + (uint32_t)(ks * 16 + acol) * 2;
                ldmat4(ah[mt], aHs + off);
                ldmat4(al[mt], aLs + off);
            }
#pragma unroll
            for (int np = 0; np < 4; np++) {
                uint32_t bh[4], bl[4];
                const uint32_t off = (uint32_t)(wx * 64 + np * 16 + brow) * (AST * 2)
                                   + (uint32_t)(ks * 16 + bcol) * 2;
                ldmat4(bh, bHs + off);
                ldmat4(bl, bLs + off);
#pragma unroll
                for (int mt = 0; mt < 2; mt++) {
                    mma_bf(acc[mt][np * 2],     ah[mt], &bh[0]);
                    mma_bf(acc[mt][np * 2 + 1], ah[mt], &bh[2]);
                    mma_bf(acc[mt][np * 2],     ah[mt], &bl[0]);
                    mma_bf(acc[mt][np * 2 + 1], ah[mt], &bl[2]);
                    mma_bf(acc[mt][np * 2],     al[mt], &bh[0]);
                    mma_bf(acc[mt][np * 2 + 1], al[mt], &bh[2]);
                }
            }
        }
        __syncthreads();
        if (c + 2 < NKC)
            load_chunk_wo(b ? buf1 : buf0, c + 2, tid, Ah, Al, Bh, Bl);
    }

#pragma unroll
    for (int mt = 0; mt < 2; mt++)
#pragma unroll
        for (int nt = 0; nt < 8; nt++)
#pragma unroll
            for (int j = 0; j < 4; j++) {
                const int row = rowBase + wy * 32 + mt * 16 + (lane >> 2) + (j >> 1) * 8;
                const int col = colBase + wx * 64 + nt * 8 + (lane & 3) * 2 + (j & 1);
                out[(size_t)row * D_MODEL + col] = acc[mt][nt][j];
            }
}

// ---------------- tensor-core flash attention (BK=128) ----------------
#define FBK    128
#define FST    72
#define QTILE  (128 * FST)             // halves
#define KTILE  (128 * FST)             // halves
#define KVSTG  (3 * KTILE)             // Kh, Kl, Vh

__device__ __forceinline__ void load_kv(__half* stagep, int kb, int tid,
        const __half* gKh, const __half* gKl, const __half* gV)
{
#pragma unroll
    for (int i = 0; i < 12; i++) {
        const int idx = i * 256 + tid;
        const int t = idx >> 10;           // 1024 cp per tile
        const int rem = idx & 1023;
        const int row = rem >> 3;
        const int seg = rem & 7;
        const __half* g = (t == 0 ? gKh : t == 1 ? gKl : gV)
                        + (size_t)(kb + row) * D_HEAD + seg * 8;
        cp_async16(smem_u32(stagep + t * KTILE + row * FST + seg * 8), g);
    }
    asm volatile("cp.async.commit_group;\n" ::: "memory");
}

__global__ __launch_bounds__(256, 1) void flash_mma()
{
    extern __shared__ __half fsm[];
    const int tid = threadIdx.x;
    const int wid = tid >> 5, lane = tid & 31;
    const int qt = blockIdx.x, h = blockIdx.y, b = blockIdx.z;
    const int bh = b * N_HEADS + h;
    const int qBase = qt * 128;
    const size_t gbase = (size_t)bh * SEQ * D_HEAD;

    const __half* gQh = g_Qh + gbase;
    const __half* gQl = g_Ql + gbase;
    const __half* gKh = g_Kh + gbase;
    const __half* gKl = g_Kl + gbase;
    const __half* gV  = g_Vh + gbase;

    __half* sQh = fsm;
    __half* sQl = fsm + QTILE;
    __half* stage0 = fsm + 2 * QTILE;
    __half* stage1 = stage0 + KVSTG;

    // Q tile load (group 0)
#pragma unroll
    for (int i = 0; i < 8; i++) {
        const int idx = i * 256 + tid;
        const int t = idx >> 10;
        const int rem = idx & 1023;
        const int row = rem >> 3;
        const int seg = rem & 7;
        const __half* g = (t ? gQl : gQh) + (size_t)(qBase + row) * D_HEAD + seg * 8;
        cp_async16(smem_u32((t ? sQl : sQh) + row * FST + seg * 8), g);
    }
    asm volatile("cp.async.commit_group;\n" ::: "memory");

    const int nkt = qt + 1;
    load_kv(stage0, 0, tid, gKh, gKl, gV);
    load_kv(stage1, FBK, tid, gKh, gKl, gV);

    const int arow = (lane & 7) + ((lane >> 3) & 1) * 8;
    const int acol = (lane >> 4) * 8;
    const int brow = (lane & 7) + (lane >> 4) * 8;
    const int bcol = ((lane >> 3) & 1) * 8;
    const int trow = (lane & 7) + ((lane >> 3) & 1) * 8;
    const int tcol = (lane >> 4) * 8;

    uint32_t qh[4][4], ql[4][4];
    float o[8][4];
#pragma unroll
    for (int nb = 0; nb < 8; nb++)
#pragma unroll
        for (int j = 0; j < 4; j++) o[nb][j] = 0.f;
    float m0 = -1e30f, m1 = -1e30f, l0 = 0.f, l1 = 0.f;

    const int row0 = qBase + wid * 16 + (lane >> 2);
    const int row1 = row0 + 8;

    for (int jt = 0; jt < nkt; jt++) {
        __half* stg = (jt & 1) ? stage1 : stage0;
        if (jt < nkt - 1) asm volatile("cp.async.wait_group 1;\n" ::: "memory");
        else              asm volatile("cp.async.wait_group 0;\n" ::: "memory");
        __syncthreads();

        if (jt == 0) {
#pragma unroll
            for (int kk = 0; kk < 4; kk++) {
                const uint32_t off = (uint32_t)(wid * 16 + arow) * (FST * 2)
                                   + (uint32_t)(kk * 16 + acol) * 2;
                ldmat4(qh[kk], smem_u32(sQh) + off);
                ldmat4(ql[kk], smem_u32(sQl) + off);
            }
        }

        const uint32_t sKh = smem_u32(stg);
        const uint32_t sKl = sKh + KTILE * 2;
        const uint32_t sV  = sKh + 2 * KTILE * 2;

        float s[16][4];
#pragma unroll
        for (int nb = 0; nb < 16; nb++)
#pragma unroll
            for (int j = 0; j < 4; j++) s[nb][j] = 0.f;

        // ---- S = Q K^T ----
#pragma unroll
        for (int kk = 0; kk < 4; kk++) {
#pragma unroll
            for (int np = 0; np < 8; np++) {
                uint32_t bkh[4], bkl[4];
                const uint32_t off = (uint32_t)(np * 16 + brow) * (FST * 2)
                                   + (uint32_t)(kk * 16 + bcol) * 2;
                ldmat4(bkh, sKh + off);
                ldmat4(bkl, sKl + off);
                mma_fp(s[np * 2],     qh[kk], &bkh[0]);
                mma_fp(s[np * 2 + 1], qh[kk], &bkh[2]);
                mma_fp(s[np * 2],     ql[kk], &bkh[0]);
                mma_fp(s[np * 2 + 1], ql[kk], &bkh[2]);
                mma_fp(s[np * 2],     qh[kk], &bkl[0]);
                mma_fp(s[np * 2 + 1], qh[kk], &bkl[2]);
            }
        }

        // ---- causal mask (diagonal tile only) ----
        if (jt == qt) {
            const int kb = jt * FBK;
#pragma unroll
            for (int nb = 0; nb < 16; nb++) {
#pragma unroll
                for (int j = 0; j < 4; j++) {
                    const int key = kb + nb * 8 + (lane & 3) * 2 + (j & 1);
                    const int qr = (j < 2) ? row0 : row1;
                    if (key > qr) s[nb][j] = -1e30f;
                }
            }
        }

        // ---- online softmax (exp2 domain) ----
        float mx0 = -1e30f, mx1 = -1e30f;
#pragma unroll
        for (int nb = 0; nb < 16; nb++) {
            mx0 = fmaxf(mx0, fmaxf(s[nb][0], s[nb][1]));
            mx1 = fmaxf(mx1, fmaxf(s[nb][2], s[nb][3]));
        }
        mx0 = fmaxf(mx0, __shfl_xor_sync(0xffffffffu, mx0, 1));
        mx0 = fmaxf(mx0, __shfl_xor_sync(0xffffffffu, mx0, 2));
        mx1 = fmaxf(mx1, __shfl_xor_sync(0xffffffffu, mx1, 1));
        mx1 = fmaxf(mx1, __shfl_xor_sync(0xffffffffu, mx1, 2));
        const float mn0 = fmaxf(m0, mx0), mn1 = fmaxf(m1, mx1);
        const float c0 = fexp2(m0 - mn0), c1 = fexp2(m1 - mn1);
        m0 = mn0; m1 = mn1;

        float sum0 = 0.f, sum1 = 0.f;
#pragma unroll
        for (int nb = 0; nb < 16; nb++) {
            s[nb][0] = fexp2(s[nb][0] - m0); sum0 += s[nb][0];
            s[nb][1] = fexp2(s[nb][1] - m0); sum0 += s[nb][1];
            s[nb][2] = fexp2(s[nb][2] - m1); sum1 += s[nb][2];
            s[nb][3] = fexp2(s[nb][3] - m1); sum1 += s[nb][3];
        }
        sum0 += __shfl_xor_sync(0xffffffffu, sum0, 1);
        sum0 += __shfl_xor_sync(0xffffffffu, sum0, 2);
        sum1 += __shfl_xor_sync(0xffffffffu, sum1, 1);
        sum1 += __shfl_xor_sync(0xffffffffu, sum1, 2);
        l0 = l0 * c0 + sum0;
        l1 = l1 * c1 + sum1;

#pragma unroll
        for (int nb = 0; nb < 8; nb++) {
            o[nb][0] *= c0; o[nb][1] *= c0;
            o[nb][2] *= c1; o[nb][3] *= c1;
        }

        // ---- O += P V ----
#pragma unroll
        for (int kk = 0; kk < 8; kk++) {
            uint32_t aH[4], aL[4];
            aH[0] = pack2(s[2 * kk][0], s[2 * kk][1]);
            aH[1] = pack2(s[2 * kk][2], s[2 * kk][3]);
            aH[2] = pack2(s[2 * kk + 1][0], s[2 * kk + 1][1]);
            aH[3] = pack2(s[2 * kk + 1][2], s[2 * kk + 1][3]);
#pragma unroll
            for (int i = 0; i < 4; i++) {
                const int nb = 2 * kk + (i >> 1);
                const int j0 = (i & 1) * 2;
                float2 f = unpack2(aH[i]);
                aL[i] = pack2(s[nb][j0] - f.x, s[nb][j0 + 1] - f.y);
            }
#pragma unroll
            for (int np = 0; np < 4; np++) {
                uint32_t bv[4];
                const uint32_t off = (uint32_t)(kk * 16 + trow) * (FST * 2)
                                   + (uint32_t)(np * 16 + tcol) * 2;
                ldmat4t(bv, sV + off);
                mma_fp(o[np * 2],     aH, &bv[0]);
                mma_fp(o[np * 2 + 1], aH, &bv[2]);
                mma_fp(o[np * 2],     aL, &bv[0]);
                mma_fp(o[np * 2 + 1], aL, &bv[2]);
            }
        }

        __syncthreads();
        if (jt + 2 < nkt)
            load_kv(stg, (jt + 2) * FBK, tid, gKh, gKl, gV);
    }

    // ---- epilogue: normalize, split-bf16, write g_Ah/g_Al ----
    const float inv0 = 1.f / l0, inv1 = 1.f / l1;
#pragma unroll
    for (int nb = 0; nb < 8; nb++) {
        const int d0 = h * D_HEAD + nb * 8 + (lane & 3) * 2;
#pragma unroll
        for (int half_m = 0; half_m < 2; half_m++) {
            const int row = half_m ? row1 : row0;
            const float inv = half_m ? inv1 : inv0;
            const float v0 = o[nb][half_m * 2] * inv;
            const float v1 = o[nb][half_m * 2 + 1] * inv;
            __nv_bfloat16 h0 = __float2bfloat16_rn(v0), h1 = __float2bfloat16_rn(v1);
            __nv_bfloat16 lo0 = __float2bfloat16_rn(v0 - __bfloat162float(h0));
            __nv_bfloat16 lo1 = __float2bfloat16_rn(v1 - __bfloat162float(h1));
            const size_t e = (size_t)(b * SEQ + row) * D_MODEL + d0;
            uint32_t uh = ((uint32_t)__bfloat16_as_ushort(h1) << 16) | __bfloat16_as_ushort(h0);
            uint32_t ul = ((uint32_t)__bfloat16_as_ushort(lo1) << 16) | __bfloat16_as_ushort(lo0);
            *(uint32_t*)(g_Ah + e) = uh;
            *(uint32_t*)(g_Al + e) = ul;
        }
    }
}

// ---------------- launch ----------------
extern "C" void kernel_launch(void* const* d_in, const int* in_sizes, int n_in,
                              void* d_out, int out_size)
{
    const float* x  = (const float*)d_in[0];
    const float* Wq = (const float*)d_in[1];
    const float* bq = (const float*)d_in[2];
    const float* Wk = (const float*)d_in[3];
    const float* bk = (const float*)d_in[4];
    const float* Wv = (const float*)d_in[5];
    const float* bv = (const float*)d_in[6];
    const float* Wo = (const float*)d_in[7];
    float* out = (float*)d_out;

    const int qkvSmem = 2 * QSTAGE;                                   // 163840
    cudaFuncSetAttribute(gemm_qkv, cudaFuncAttributeMaxDynamicSharedMemorySize, qkvSmem);
    const int woSmem = 2 * BUFB;                                      // 81920
    cudaFuncSetAttribute(gemm_wo, cudaFuncAttributeMaxDynamicSharedMemorySize, woSmem);
    const int flashSmem = (2 * QTILE + 2 * KVSTG) * (int)sizeof(__half);  // 147456
    cudaFuncSetAttribute(flash_mma, cudaFuncAttributeMaxDynamicSharedMemorySize, flashSmem);

    cvt_rm<<<M_ROWS * D_MODEL / 4 / 256, 256>>>(x);
    cvt_wt<<<dim3(D_MODEL / 32, D_MODEL / 32, 4), 256>>>(Wq, Wk, Wv, Wo);
    gemm_qkv<<<dim3(D_MODEL / 128, M_ROWS / 128), 256, qkvSmem>>>(bq, bk, bv);
    flash_mma<<<dim3(SEQ / 128, N_HEADS, BATCH), 256, flashSmem>>>();
    gemm_wo<<<dim3(D_MODEL / 128, M_ROWS / 128), 256, woSmem>>>(out);
}

// round 10
// speedup vs baseline: 1.2899x; 1.0658x over previous
#include <cuda_runtime.h>
#include <cuda_bf16.h>
#include <cuda_fp16.h>
#include <cstdint>

#define D_MODEL 1024
#define N_HEADS 16
#define D_HEAD  64
#define BATCH   2
#define SEQ     2048
#define M_ROWS  (BATCH * SEQ)      // 4096

// Q pre-scale: 1/sqrt(Dh) * log2(e)  (softmax computed in exp2 domain)
#define QSCALE 0.1803368801111204f

// ---------------- scratch (no allocations allowed) ----------------
__device__ __half g_Qh[(size_t)BATCH * N_HEADS * SEQ * D_HEAD];
__device__ __half g_Ql[(size_t)BATCH * N_HEADS * SEQ * D_HEAD];
__device__ __half g_Kh[(size_t)BATCH * N_HEADS * SEQ * D_HEAD];   // single fp16 K
__device__ __half g_Vh[(size_t)BATCH * N_HEADS * SEQ * D_HEAD];   // single fp16 V

__device__ __nv_bfloat16 g_xh[(size_t)M_ROWS * D_MODEL];
__device__ __nv_bfloat16 g_xl[(size_t)M_ROWS * D_MODEL];
__device__ __nv_bfloat16 g_Ah[(size_t)M_ROWS * D_MODEL];
__device__ __nv_bfloat16 g_Al[(size_t)M_ROWS * D_MODEL];
__device__ __nv_bfloat16 g_Wth[(size_t)4 * D_MODEL * D_MODEL];  // W^T hi, [4][n][k]
__device__ __nv_bfloat16 g_Wtl[(size_t)4 * D_MODEL * D_MODEL];  // W^T lo

// ---------------- helpers ----------------
__device__ __forceinline__ uint32_t smem_u32(const void* p) {
    uint32_t a;
    asm("{ .reg .u64 t; cvta.to.shared.u64 t, %1; cvt.u32.u64 %0, t; }" : "=r"(a) : "l"(p));
    return a;
}
__device__ __forceinline__ void cp_async16(uint32_t sa, const void* g) {
    asm volatile("cp.async.cg.shared.global [%0], [%1], 16;\n" :: "r"(sa), "l"(g));
}
__device__ __forceinline__ void ldmat4(uint32_t* r, uint32_t addr) {
    asm volatile("ldmatrix.sync.aligned.m8n8.x4.shared.b16 {%0,%1,%2,%3}, [%4];"
        : "=r"(r[0]), "=r"(r[1]), "=r"(r[2]), "=r"(r[3]) : "r"(addr));
}
__device__ __forceinline__ void ldmat4t(uint32_t* r, uint32_t addr) {
    asm volatile("ldmatrix.sync.aligned.m8n8.x4.trans.shared.b16 {%0,%1,%2,%3}, [%4];"
        : "=r"(r[0]), "=r"(r[1]), "=r"(r[2]), "=r"(r[3]) : "r"(addr));
}
__device__ __forceinline__ void mma_bf(float* c, const uint32_t* a, const uint32_t* b) {
    asm volatile("mma.sync.aligned.m16n8k16.row.col.f32.bf16.bf16.f32 "
        "{%0,%1,%2,%3}, {%4,%5,%6,%7}, {%8,%9}, {%0,%1,%2,%3};"
        : "+f"(c[0]), "+f"(c[1]), "+f"(c[2]), "+f"(c[3])
        : "r"(a[0]), "r"(a[1]), "r"(a[2]), "r"(a[3]), "r"(b[0]), "r"(b[1]));
}
__device__ __forceinline__ void mma_fp(float* c, const uint32_t* a, const uint32_t* b) {
    asm volatile("mma.sync.aligned.m16n8k16.row.col.f32.f16.f16.f32 "
        "{%0,%1,%2,%3}, {%4,%5,%6,%7}, {%8,%9}, {%0,%1,%2,%3};"
        : "+f"(c[0]), "+f"(c[1]), "+f"(c[2]), "+f"(c[3])
        : "r"(a[0]), "r"(a[1]), "r"(a[2]), "r"(a[3]), "r"(b[0]), "r"(b[1]));
}
__device__ __forceinline__ float fexp2(float x) {
    float r; asm("ex2.approx.f32 %0, %1;" : "=f"(r) : "f"(x)); return r;
}
__device__ __forceinline__ uint32_t pack2(float x, float y) {
    uint32_t r; asm("cvt.rn.f16x2.f32 %0, %1, %2;" : "=r"(r) : "f"(y), "f"(x)); return r;
}
__device__ __forceinline__ float2 unpack2(uint32_t u) {
    __half2 h; *reinterpret_cast<uint32_t*>(&h) = u;
    return __half22float2(h);
}

// ---------------- conversion kernels ----------------
__global__ __launch_bounds__(256) void cvt_rm(const float* __restrict__ src)
{
    const size_t i4 = (size_t)blockIdx.x * blockDim.x + threadIdx.x;
    if (i4 < (size_t)M_ROWS * D_MODEL / 4) {
        float4 v = ((const float4*)src)[i4];
        float vv[4] = {v.x, v.y, v.z, v.w};
#pragma unroll
        for (int j = 0; j < 4; j++) {
            __nv_bfloat16 h = __float2bfloat16_rn(vv[j]);
            g_xh[i4 * 4 + j] = h;
            g_xl[i4 * 4 + j] = __float2bfloat16_rn(vv[j] - __bfloat162float(h));
        }
    }
}

__global__ __launch_bounds__(256) void cvt_wt(const float* __restrict__ Wq,
                                              const float* __restrict__ Wk,
                                              const float* __restrict__ Wv,
                                              const float* __restrict__ Wo)
{
    __shared__ float t[32][33];
    const int z = blockIdx.z;
    const float* W = (z == 0) ? Wq : (z == 1) ? Wk : (z == 2) ? Wv : Wo;
    __nv_bfloat16* hi = g_Wth + (size_t)z * D_MODEL * D_MODEL;
    __nv_bfloat16* lo = g_Wtl + (size_t)z * D_MODEL * D_MODEL;
    const int n0 = blockIdx.x * 32, k0 = blockIdx.y * 32;
    const int tx = threadIdx.x & 31, ty = threadIdx.x >> 5;
    for (int r = ty; r < 32; r += 8)
        t[r][tx] = W[(size_t)(k0 + r) * D_MODEL + n0 + tx];
    __syncthreads();
    for (int r = ty; r < 32; r += 8) {
        float v = t[tx][r];
        __nv_bfloat16 h = __float2bfloat16_rn(v);
        const size_t o = (size_t)(n0 + r) * D_MODEL + k0 + tx;
        hi[o] = h;
        lo[o] = __float2bfloat16_rn(v - __bfloat162float(h));
    }
}

// ---------------- shared GEMM constants ----------------
#define AST   40
#define TILEB (128 * AST * 2)          // 10240 B per 128x32 bf16 tile
#define KC    32
#define NKC   (D_MODEL / KC)           // 32 chunks

// ---------------- fused QKV GEMM ----------------
#define QSTAGE (8 * TILEB)             // 81920 B

__device__ __forceinline__ void load_chunk_qkv(uint32_t bufbase, int c, int tid,
        const __nv_bfloat16* const* gs)
{
#pragma unroll
    for (int i = 0; i < 16; i++) {
        const int idx = i * 256 + tid;
        const int t = idx >> 9;
        const int rem = idx & 511;
        const int row = rem >> 2;
        const int seg = rem & 3;
        cp_async16(bufbase + t * TILEB + row * (AST * 2) + seg * 16,
                   gs[t] + (size_t)row * D_MODEL + c * KC + seg * 8);
    }
    asm volatile("cp.async.commit_group;\n" ::: "memory");
}

__global__ __launch_bounds__(256, 1) void gemm_qkv(
        const float* __restrict__ bq, const float* __restrict__ bk,
        const float* __restrict__ bv)
{
    extern __shared__ char smem[];
    const uint32_t sb = smem_u32(smem);
    const int tid = threadIdx.x;
    const int wid = tid >> 5, lane = tid & 31;
    const int wy = wid & 3, wx = wid >> 2;
    const int rowBase = blockIdx.y * 128;
    const int colBase = blockIdx.x * 128;

    const __nv_bfloat16* gs[8];
    gs[0] = g_xh + (size_t)rowBase * D_MODEL;
    gs[1] = g_xl + (size_t)rowBase * D_MODEL;
#pragma unroll
    for (int z = 0; z < 3; z++) {
        gs[2 + 2 * z] = g_Wth + (size_t)z * D_MODEL * D_MODEL + (size_t)colBase * D_MODEL;
        gs[3 + 2 * z] = g_Wtl + (size_t)z * D_MODEL * D_MODEL + (size_t)colBase * D_MODEL;
    }

    const uint32_t buf0 = sb, buf1 = sb + QSTAGE;

    float acc[3][2][8][4];
#pragma unroll
    for (int z = 0; z < 3; z++)
#pragma unroll
        for (int mt = 0; mt < 2; mt++)
#pragma unroll
            for (int nt = 0; nt < 8; nt++)
#pragma unroll
                for (int j = 0; j < 4; j++) acc[z][mt][nt][j] = 0.f;

    load_chunk_qkv(buf0, 0, tid, gs);
    load_chunk_qkv(buf1, 1, tid, gs);

    const int arow = (lane & 7) + ((lane >> 3) & 1) * 8;
    const int acol = (lane >> 4) * 8;
    const int brow = (lane & 7) + (lane >> 4) * 8;
    const int bcol = ((lane >> 3) & 1) * 8;

    for (int c = 0; c < NKC; c++) {
        const int b = c & 1;
        if (c < NKC - 1) asm volatile("cp.async.wait_group 1;\n" ::: "memory");
        else             asm volatile("cp.async.wait_group 0;\n" ::: "memory");
        __syncthreads();

        const uint32_t base = b ? buf1 : buf0;

#pragma unroll
        for (int ks = 0; ks < 2; ks++) {
            uint32_t ah[2][4], al[2][4];
#pragma unroll
            for (int mt = 0; mt < 2; mt++) {
                const uint32_t off = (uint32_t)(wy * 32 + mt * 16 + arow) * (AST * 2)
                                   + (uint32_t)(ks * 16 + acol) * 2;
                ldmat4(ah[mt], base + off);
                ldmat4(al[mt], base + TILEB + off);
            }
#pragma unroll
            for (int z = 0; z < 3; z++) {
#pragma unroll
                for (int np = 0; np < 4; np++) {
                    uint32_t bh[4], bl[4];
                    const uint32_t off = (uint32_t)(wx * 64 + np * 16 + brow) * (AST * 2)
                                       + (uint32_t)(ks * 16 + bcol) * 2;
                    ldmat4(bh, base + (2 + 2 * z) * TILEB + off);
                    ldmat4(bl, base + (3 + 2 * z) * TILEB + off);
#pragma unroll
                    for (int mt = 0; mt < 2; mt++) {
                        mma_bf(acc[z][mt][np * 2],     ah[mt], &bh[0]);
                        mma_bf(acc[z][mt][np * 2 + 1], ah[mt], &bh[2]);
                        mma_bf(acc[z][mt][np * 2],     ah[mt], &bl[0]);
                        mma_bf(acc[z][mt][np * 2 + 1], ah[mt], &bl[2]);
                        mma_bf(acc[z][mt][np * 2],     al[mt], &bh[0]);
                        mma_bf(acc[z][mt][np * 2 + 1], al[mt], &bh[2]);
                    }
                }
            }
        }
        __syncthreads();
        if (c + 2 < NKC)
            load_chunk_qkv(b ? buf1 : buf0, c + 2, tid, gs);
    }

    // epilogue: Q split-fp16, K/V single fp16
#pragma unroll
    for (int z = 0; z < 3; z++) {
        const float* bias = (z == 0) ? bq : (z == 1) ? bk : bv;
        __half* dH = (z == 0) ? g_Qh : (z == 1) ? g_Kh : g_Vh;
        const float sc = (z == 0) ? QSCALE : 1.0f;
#pragma unroll
        for (int mt = 0; mt < 2; mt++) {
#pragma unroll
            for (int nt = 0; nt < 8; nt++) {
                const int col0 = colBase + wx * 64 + nt * 8 + (lane & 3) * 2;
                const int hh = col0 >> 6, d0 = col0 & (D_HEAD - 1);
                const float b0 = bias[col0], b1 = bias[col0 + 1];
#pragma unroll
                for (int half_m = 0; half_m < 2; half_m++) {
                    const int row = rowBase + wy * 32 + mt * 16 + (lane >> 2) + half_m * 8;
                    const int bb = row >> 11, s = row & (SEQ - 1);
                    float v0 = (acc[z][mt][nt][half_m * 2]     + b0) * sc;
                    float v1 = (acc[z][mt][nt][half_m * 2 + 1] + b1) * sc;
                    const uint32_t hpair = pack2(v0, v1);
                    const size_t e = (((size_t)(bb * N_HEADS + hh)) * SEQ + s) * D_HEAD + d0;
                    *(uint32_t*)(dH + e) = hpair;
                    if (z == 0) {
                        float2 f = unpack2(hpair);
                        *(uint32_t*)(g_Ql + e) = pack2(v0 - f.x, v1 - f.y);
                    }
                }
            }
        }
    }
}

// ---------------- Wo GEMM (2 CTAs/SM) ----------------
#define BUFB  (4 * TILEB)

__device__ __forceinline__ void load_chunk_wo(uint32_t bufbase, int c, int tid,
        const __nv_bfloat16* g0, const __nv_bfloat16* g1,
        const __nv_bfloat16* g2, const __nv_bfloat16* g3)
{
    const __nv_bfloat16* gs[4] = {g0, g1, g2, g3};
#pragma unroll
    for (int i = 0; i < 8; i++) {
        const int idx = i * 256 + tid;
        const int t = idx >> 9;
        const int rem = idx & 511;
        const int row = rem >> 2;
        const int seg = rem & 3;
        cp_async16(bufbase + t * TILEB + row * (AST * 2) + seg * 16,
                   gs[t] + (size_t)row * D_MODEL + c * KC + seg * 8);
    }
    asm volatile("cp.async.commit_group;\n" ::: "memory");
}

__global__ __launch_bounds__(256, 2) void gemm_wo(float* __restrict__ out)
{
    extern __shared__ char smem[];
    const uint32_t sb = smem_u32(smem);
    const int tid = threadIdx.x;
    const int wid = tid >> 5, lane = tid & 31;
    const int wy = wid & 3, wx = wid >> 2;
    const int rowBase = blockIdx.y * 128;
    const int colBase = blockIdx.x * 128;

    const __nv_bfloat16* Ah = g_Ah + (size_t)rowBase * D_MODEL;
    const __nv_bfloat16* Al = g_Al + (size_t)rowBase * D_MODEL;
    const __nv_bfloat16* Bh = g_Wth + (size_t)3 * D_MODEL * D_MODEL + (size_t)colBase * D_MODEL;
    const __nv_bfloat16* Bl = g_Wtl + (size_t)3 * D_MODEL * D_MODEL + (size_t)colBase * D_MODEL;

    const uint32_t buf0 = sb, buf1 = sb + BUFB;

    float acc[2][8][4];
#pragma unroll
    for (int mt = 0; mt < 2; mt++)
#pragma unroll
        for (int nt = 0; nt < 8; nt++)
#pragma unroll
            for (int j = 0; j < 4; j++) acc[mt][nt][j] = 0.f;

    load_chunk_wo(buf0, 0, tid, Ah, Al, Bh, Bl);
    load_chunk_wo(buf1, 1, tid, Ah, Al, Bh, Bl);

    const int arow = (lane & 7) + ((lane >> 3) & 1) * 8;
    const int acol = (lane >> 4) * 8;
    const int brow = (lane & 7) + (lane >> 4) * 8;
    const int bcol = ((lane >> 3) & 1) * 8;

    for (int c = 0; c < NKC; c++) {
        const int b = c & 1;
        if (c < NKC - 1) asm volatile("cp.async.wait_group 1;\n" ::: "memory");
        else             asm volatile("cp.async.wait_group 0;\n" ::: "memory");
        __syncthreads();

        const uint32_t base = b ? buf1 : buf0;
        const uint32_t aHs = base,             aLs = base + TILEB;
        const uint32_t bHs = base + 2 * TILEB, bLs = base + 3 * TILEB;

#pragma unroll
        for (int ks = 0; ks < 2; ks++) {
            uint32_t ah[2][4], al[2][4];
#pragma unroll
            for (int mt = 0; mt < 2; mt++) {
                const uint32_t off = (uint32_t)(wy * 32 + mt * 16 + arow) * (AST * 2)
                                   + (uint32_t)(ks * 16 + acol) * 2;
                ldmat4(ah[mt], aHs + off);
                ldmat4(al[mt], aLs + off);
            }
#pragma unroll
            for (int np = 0; np < 4; np++) {
                uint32_t bh[4], bl[4];
                const uint32_t off = (uint32_t)(wx * 64 + np * 16 + brow) * (AST * 2)
                                   + (uint32_t)(ks * 16 + bcol) * 2;
                ldmat4(bh, bHs + off);
                ldmat4(bl, bLs + off);
#pragma unroll
                for (int mt = 0; mt < 2; mt++) {
                    mma_bf(acc[mt][np * 2],     ah[mt], &bh[0]);
                    mma_bf(acc[mt][np * 2 + 1], ah[mt], &bh[2]);
                    mma_bf(acc[mt][np * 2],     ah[mt], &bl[0]);
                    mma_bf(acc[mt][np * 2 + 1], ah[mt], &bl[2]);
                    mma_bf(acc[mt][np * 2],     al[mt], &bh[0]);
                    mma_bf(acc[mt][np * 2 + 1], al[mt], &bh[2]);
                }
            }
        }
        __syncthreads();
        if (c + 2 < NKC)
            load_chunk_wo(b ? buf1 : buf0, c + 2, tid, Ah, Al, Bh, Bl);
    }

#pragma unroll
    for (int mt = 0; mt < 2; mt++)
#pragma unroll
        for (int nt = 0; nt < 8; nt++)
#pragma unroll
            for (int j = 0; j < 4; j++) {
                const int row = rowBase + wy * 32 + mt * 16 + (lane >> 2) + (j >> 1) * 8;
                const int col = colBase + wx * 64 + nt * 8 + (lane & 3) * 2 + (j & 1);
                out[(size_t)row * D_MODEL + col] = acc[mt][nt][j];
            }
}

// ---------------- tensor-core flash attention (BK=128, K single fp16) ----------------
#define FBK    128
#define FST    72
#define QTILE  (128 * FST)             // halves
#define KTILE  (128 * FST)             // halves
#define KVSTG  (2 * KTILE)             // Kh, Vh

__device__ __forceinline__ void load_kv(__half* stagep, int kb, int tid,
        const __half* gK, const __half* gV)
{
#pragma unroll
    for (int i = 0; i < 8; i++) {
        const int idx = i * 256 + tid;
        const int t = idx >> 10;           // 1024 cp per tile
        const int rem = idx & 1023;
        const int row = rem >> 3;
        const int seg = rem & 7;
        const __half* g = (t == 0 ? gK : gV) + (size_t)(kb + row) * D_HEAD + seg * 8;
        cp_async16(smem_u32(stagep + t * KTILE + row * FST + seg * 8), g);
    }
    asm volatile("cp.async.commit_group;\n" ::: "memory");
}

__global__ __launch_bounds__(256, 1) void flash_mma()
{
    extern __shared__ __half fsm[];
    const int tid = threadIdx.x;
    const int wid = tid >> 5, lane = tid & 31;
    const int qt = blockIdx.x, h = blockIdx.y, b = blockIdx.z;
    const int bh = b * N_HEADS + h;
    const int qBase = qt * 128;
    const size_t gbase = (size_t)bh * SEQ * D_HEAD;

    const __half* gQh = g_Qh + gbase;
    const __half* gQl = g_Ql + gbase;
    const __half* gK  = g_Kh + gbase;
    const __half* gV  = g_Vh + gbase;

    __half* sQh = fsm;
    __half* sQl = fsm + QTILE;
    __half* stage0 = fsm + 2 * QTILE;
    __half* stage1 = stage0 + KVSTG;

    // Q tile load (group 0)
#pragma unroll
    for (int i = 0; i < 8; i++) {
        const int idx = i * 256 + tid;
        const int t = idx >> 10;
        const int rem = idx & 1023;
        const int row = rem >> 3;
        const int seg = rem & 7;
        const __half* g = (t ? gQl : gQh) + (size_t)(qBase + row) * D_HEAD + seg * 8;
        cp_async16(smem_u32((t ? sQl : sQh) + row * FST + seg * 8), g);
    }
    asm volatile("cp.async.commit_group;\n" ::: "memory");

    const int nkt = qt + 1;
    load_kv(stage0, 0, tid, gK, gV);
    load_kv(stage1, FBK, tid, gK, gV);

    const int arow = (lane & 7) + ((lane >> 3) & 1) * 8;
    const int acol = (lane >> 4) * 8;
    const int brow = (lane & 7) + (lane >> 4) * 8;
    const int bcol = ((lane >> 3) & 1) * 8;
    const int trow = (lane & 7) + ((lane >> 3) & 1) * 8;
    const int tcol = (lane >> 4) * 8;

    uint32_t qh[4][4], ql[4][4];
    float o[8][4];
#pragma unroll
    for (int nb = 0; nb < 8; nb++)
#pragma unroll
        for (int j = 0; j < 4; j++) o[nb][j] = 0.f;
    float m0 = -1e30f, m1 = -1e30f, l0 = 0.f, l1 = 0.f;

    const int row0 = qBase + wid * 16 + (lane >> 2);
    const int row1 = row0 + 8;

    for (int jt = 0; jt < nkt; jt++) {
        __half* stg = (jt & 1) ? stage1 : stage0;
        if (jt < nkt - 1) asm volatile("cp.async.wait_group 1;\n" ::: "memory");
        else              asm volatile("cp.async.wait_group 0;\n" ::: "memory");
        __syncthreads();

        if (jt == 0) {
#pragma unroll
            for (int kk = 0; kk < 4; kk++) {
                const uint32_t off = (uint32_t)(wid * 16 + arow) * (FST * 2)
                                   + (uint32_t)(kk * 16 + acol) * 2;
                ldmat4(qh[kk], smem_u32(sQh) + off);
                ldmat4(ql[kk], smem_u32(sQl) + off);
            }
        }

        const uint32_t sK = smem_u32(stg);
        const uint32_t sV = sK + KTILE * 2;

        float s[16][4];
#pragma unroll
        for (int nb = 0; nb < 16; nb++)
#pragma unroll
            for (int j = 0; j < 4; j++) s[nb][j] = 0.f;

        // ---- S = Q K^T : 2 passes (qh*k + ql*k) ----
#pragma unroll
        for (int kk = 0; kk < 4; kk++) {
#pragma unroll
            for (int np = 0; np < 8; np++) {
                uint32_t bk4[4];
                const uint32_t off = (uint32_t)(np * 16 + brow) * (FST * 2)
                                   + (uint32_t)(kk * 16 + bcol) * 2;
                ldmat4(bk4, sK + off);
                mma_fp(s[np * 2],     qh[kk], &bk4[0]);
                mma_fp(s[np * 2 + 1], qh[kk], &bk4[2]);
                mma_fp(s[np * 2],     ql[kk], &bk4[0]);
                mma_fp(s[np * 2 + 1], ql[kk], &bk4[2]);
            }
        }

        // ---- causal mask (diagonal tile only) ----
        if (jt == qt) {
            const int kb = jt * FBK;
#pragma unroll
            for (int nb = 0; nb < 16; nb++) {
#pragma unroll
                for (int j = 0; j < 4; j++) {
                    const int key = kb + nb * 8 + (lane & 3) * 2 + (j & 1);
                    const int qr = (j < 2) ? row0 : row1;
                    if (key > qr) s[nb][j] = -1e30f;
                }
            }
        }

        // ---- online softmax (exp2 domain) ----
        float mx0 = -1e30f, mx1 = -1e30f;
#pragma unroll
        for (int nb = 0; nb < 16; nb++) {
            mx0 = fmaxf(mx0, fmaxf(s[nb][0], s[nb][1]));
            mx1 = fmaxf(mx1, fmaxf(s[nb][2], s[nb][3]));
        }
        mx0 = fmaxf(mx0, __shfl_xor_sync(0xffffffffu, mx0, 1));
        mx0 = fmaxf(mx0, __shfl_xor_sync(0xffffffffu, mx0, 2));
        mx1 = fmaxf(mx1, __shfl_xor_sync(0xffffffffu, mx1, 1));
        mx1 = fmaxf(mx1, __shfl_xor_sync(0xffffffffu, mx1, 2));
        const float mn0 = fmaxf(m0, mx0), mn1 = fmaxf(m1, mx1);
        const float c0 = fexp2(m0 - mn0), c1 = fexp2(m1 - mn1);
        m0 = mn0; m1 = mn1;

        float sum0 = 0.f, sum1 = 0.f;
#pragma unroll
        for (int nb = 0; nb < 16; nb++) {
            s[nb][0] = fexp2(s[nb][0] - m0); sum0 += s[nb][0];
            s[nb][1] = fexp2(s[nb][1] - m0); sum0 += s[nb][1];
            s[nb][2] = fexp2(s[nb][2] - m1); sum1 += s[nb][2];
            s[nb][3] = fexp2(s[nb][3] - m1); sum1 += s[nb][3];
        }
        sum0 += __shfl_xor_sync(0xffffffffu, sum0, 1);
        sum0 += __shfl_xor_sync(0xffffffffu, sum0, 2);
        sum1 += __shfl_xor_sync(0xffffffffu, sum1, 1);
        sum1 += __shfl_xor_sync(0xffffffffu, sum1, 2);
        l0 = l0 * c0 + sum0;
        l1 = l1 * c1 + sum1;

#pragma unroll
        for (int nb = 0; nb < 8; nb++) {
            o[nb][0] *= c0; o[nb][1] *= c0;
            o[nb][2] *= c1; o[nb][3] *= c1;
        }

        // ---- O += P V (P split, V single) ----
#pragma unroll
        for (int kk = 0; kk < 8; kk++) {
            uint32_t aH[4], aL[4];
            aH[0] = pack2(s[2 * kk][0], s[2 * kk][1]);
            aH[1] = pack2(s[2 * kk][2], s[2 * kk][3]);
            aH[2] = pack2(s[2 * kk + 1][0], s[2 * kk + 1][1]);
            aH[3] = pack2(s[2 * kk + 1][2], s[2 * kk + 1][3]);
#pragma unroll
            for (int i = 0; i < 4; i++) {
                const int nb = 2 * kk + (i >> 1);
                const int j0 = (i & 1) * 2;
                float2 f = unpack2(aH[i]);
                aL[i] = pack2(s[nb][j0] - f.x, s[nb][j0 + 1] - f.y);
            }
#pragma unroll
            for (int np = 0; np < 4; np++) {
                uint32_t bv[4];
                const uint32_t off = (uint32_t)(kk * 16 + trow) * (FST * 2)
                                   + (uint32_t)(np * 16 + tcol) * 2;
                ldmat4t(bv, sV + off);
                mma_fp(o[np * 2],     aH, &bv[0]);
                mma_fp(o[np * 2 + 1], aH, &bv[2]);
                mma_fp(o[np * 2],     aL, &bv[0]);
                mma_fp(o[np * 2 + 1], aL, &bv[2]);
            }
        }

        __syncthreads();
        if (jt + 2 < nkt)
            load_kv(stg, (jt + 2) * FBK, tid, gK, gV);
    }

    // ---- epilogue: normalize, split-bf16, write g_Ah/g_Al ----
    const float inv0 = 1.f / l0, inv1 = 1.f / l1;
#pragma unroll
    for (int nb = 0; nb < 8; nb++) {
        const int d0 = h * D_HEAD + nb * 8 + (lane & 3) * 2;
#pragma unroll
        for (int half_m = 0; half_m < 2; half_m++) {
            const int row = half_m ? row1 : row0;
            const float inv = half_m ? inv1 : inv0;
            const float v0 = o[nb][half_m * 2] * inv;
            const float v1 = o[nb][half_m * 2 + 1] * inv;
            __nv_bfloat16 h0 = __float2bfloat16_rn(v0), h1 = __float2bfloat16_rn(v1);
            __nv_bfloat16 lo0 = __float2bfloat16_rn(v0 - __bfloat162float(h0));
            __nv_bfloat16 lo1 = __float2bfloat16_rn(v1 - __bfloat162float(h1));
            const size_t e = (size_t)(b * SEQ + row) * D_MODEL + d0;
            uint32_t uh = ((uint32_t)__bfloat16_as_ushort(h1) << 16) | __bfloat16_as_ushort(h0);
            uint32_t ul = ((uint32_t)__bfloat16_as_ushort(lo1) << 16) | __bfloat16_as_ushort(lo0);
            *(uint32_t*)(g_Ah + e) = uh;
            *(uint32_t*)(g_Al + e) = ul;
        }
    }
}

// ---------------- launch ----------------
extern "C" void kernel_launch(void* const* d_in, const int* in_sizes, int n_in,
                              void* d_out, int out_size)
{
    const float* x  = (const float*)d_in[0];
    const float* Wq = (const float*)d_in[1];
    const float* bq = (const float*)d_in[2];
    const float* Wk = (const float*)d_in[3];
    const float* bk = (const float*)d_in[4];
    const float* Wv = (const float*)d_in[5];
    const float* bv = (const float*)d_in[6];
    const float* Wo = (const float*)d_in[7];
    float* out = (float*)d_out;

    const int qkvSmem = 2 * QSTAGE;                                   // 163840
    cudaFuncSetAttribute(gemm_qkv, cudaFuncAttributeMaxDynamicSharedMemorySize, qkvSmem);
    const int woSmem = 2 * BUFB;                                      // 81920
    cudaFuncSetAttribute(gemm_wo, cudaFuncAttributeMaxDynamicSharedMemorySize, woSmem);
    const int flashSmem = (2 * QTILE + 2 * KVSTG) * (int)sizeof(__half);  // 110592
    cudaFuncSetAttribute(flash_mma, cudaFuncAttributeMaxDynamicSharedMemorySize, flashSmem);

    cvt_rm<<<M_ROWS * D_MODEL / 4 / 256, 256>>>(x);
    cvt_wt<<<dim3(D_MODEL / 32, D_MODEL / 32, 4), 256>>>(Wq, Wk, Wv, Wo);
    gemm_qkv<<<dim3(D_MODEL / 128, M_ROWS / 128), 256, qkvSmem>>>(bq, bk, bv);
    flash_mma<<<dim3(SEQ / 128, N_HEADS, BATCH), 256, flashSmem>>>();
    gemm_wo<<<dim3(D_MODEL / 128, M_ROWS / 128), 256, woSmem>>>(out);
}

// round 12
// speedup vs baseline: 1.6029x; 1.2426x over previous
#include <cuda_runtime.h>
#include <cuda_fp16.h>
#include <cstdint>

#define D_MODEL 1024
#define N_HEADS 16
#define D_HEAD  64
#define BATCH   2
#define SEQ     2048
#define M_ROWS  (BATCH * SEQ)      // 4096

// Q pre-scale: 1/sqrt(Dh) * log2(e)  (softmax computed in exp2 domain)
#define QSCALE 0.1803368801111204f

// ---------------- scratch (no allocations allowed) ----------------
__device__ __half g_Qh[(size_t)BATCH * N_HEADS * SEQ * D_HEAD];
__device__ __half g_Ql[(size_t)BATCH * N_HEADS * SEQ * D_HEAD];
__device__ __half g_Kh[(size_t)BATCH * N_HEADS * SEQ * D_HEAD];   // single fp16 K
__device__ __half g_Vh[(size_t)BATCH * N_HEADS * SEQ * D_HEAD];   // single fp16 V

__device__ __half g_xh[(size_t)M_ROWS * D_MODEL];                 // x split fp16
__device__ __half g_xl[(size_t)M_ROWS * D_MODEL];
__device__ __half g_Ah[(size_t)M_ROWS * D_MODEL];                 // attn out split fp16
__device__ __half g_Al[(size_t)M_ROWS * D_MODEL];
__device__ __half g_Wt[(size_t)4 * D_MODEL * D_MODEL];            // W^T single fp16 [4][n][k]

// ---------------- helpers ----------------
__device__ __forceinline__ uint32_t smem_u32(const void* p) {
    uint32_t a;
    asm("{ .reg .u64 t; cvta.to.shared.u64 t, %1; cvt.u32.u64 %0, t; }" : "=r"(a) : "l"(p));
    return a;
}
__device__ __forceinline__ void cp_async16(uint32_t sa, const void* g) {
    asm volatile("cp.async.cg.shared.global [%0], [%1], 16;\n" :: "r"(sa), "l"(g));
}
__device__ __forceinline__ void ldmat4(uint32_t* r, uint32_t addr) {
    asm volatile("ldmatrix.sync.aligned.m8n8.x4.shared.b16 {%0,%1,%2,%3}, [%4];"
        : "=r"(r[0]), "=r"(r[1]), "=r"(r[2]), "=r"(r[3]) : "r"(addr));
}
__device__ __forceinline__ void ldmat4t(uint32_t* r, uint32_t addr) {
    asm volatile("ldmatrix.sync.aligned.m8n8.x4.trans.shared.b16 {%0,%1,%2,%3}, [%4];"
        : "=r"(r[0]), "=r"(r[1]), "=r"(r[2]), "=r"(r[3]) : "r"(addr));
}
__device__ __forceinline__ void mma_fp(float* c, const uint32_t* a, const uint32_t* b) {
    asm volatile("mma.sync.aligned.m16n8k16.row.col.f32.f16.f16.f32 "
        "{%0,%1,%2,%3}, {%4,%5,%6,%7}, {%8,%9}, {%0,%1,%2,%3};"
        : "+f"(c[0]), "+f"(c[1]), "+f"(c[2]), "+f"(c[3])
        : "r"(a[0]), "r"(a[1]), "r"(a[2]), "r"(a[3]), "r"(b[0]), "r"(b[1]));
}
__device__ __forceinline__ float fexp2(float x) {
    float r; asm("ex2.approx.f32 %0, %1;" : "=f"(r) : "f"(x)); return r;
}
__device__ __forceinline__ uint32_t pack2(float x, float y) {
    uint32_t r; asm("cvt.rn.f16x2.f32 %0, %1, %2;" : "=r"(r) : "f"(y), "f"(x)); return r;
}
__device__ __forceinline__ float2 unpack2(uint32_t u) {
    __half2 h; *reinterpret_cast<uint32_t*>(&h) = u;
    return __half22float2(h);
}

// ---------------- conversion kernels ----------------
__global__ __launch_bounds__(256) void cvt_rm(const float* __restrict__ src)
{
    const size_t i4 = (size_t)blockIdx.x * blockDim.x + threadIdx.x;
    if (i4 < (size_t)M_ROWS * D_MODEL / 4) {
        float4 v = ((const float4*)src)[i4];
        float vv[4] = {v.x, v.y, v.z, v.w};
#pragma unroll
        for (int j = 0; j < 4; j++) {
            __half h = __float2half_rn(vv[j]);
            g_xh[i4 * 4 + j] = h;
            g_xl[i4 * 4 + j] = __float2half_rn(vv[j] - __half2float(h));
        }
    }
}

// transpose-convert to single fp16: W[k][n] -> Wt[n][k]
__global__ __launch_bounds__(256) void cvt_wt(const float* __restrict__ Wq,
                                              const float* __restrict__ Wk,
                                              const float* __restrict__ Wv,
                                              const float* __restrict__ Wo)
{
    __shared__ float t[32][33];
    const int z = blockIdx.z;
    const float* W = (z == 0) ? Wq : (z == 1) ? Wk : (z == 2) ? Wv : Wo;
    __half* dst = g_Wt + (size_t)z * D_MODEL * D_MODEL;
    const int n0 = blockIdx.x * 32, k0 = blockIdx.y * 32;
    const int tx = threadIdx.x & 31, ty = threadIdx.x >> 5;
    for (int r = ty; r < 32; r += 8)
        t[r][tx] = W[(size_t)(k0 + r) * D_MODEL + n0 + tx];
    __syncthreads();
    for (int r = ty; r < 32; r += 8)
        dst[(size_t)(n0 + r) * D_MODEL + k0 + tx] = __float2half_rn(t[tx][r]);
}

// ---------------- shared GEMM constants ----------------
#define AST   40
#define TILEB (128 * AST * 2)          // 10240 B per 128x32 fp16 tile
#define KC    32
#define NKC   (D_MODEL / KC)           // 32 chunks

// ---------------- fused QKV GEMM: A split (2-pass), W single ----------------
// stage layout: [Ah, Al, BQ, BK, BV] x TILEB
#define QSTAGE (5 * TILEB)             // 51200 B

__device__ __forceinline__ void load_chunk_qkv(uint32_t bufbase, int c, int tid,
        const __half* const* gs)
{
#pragma unroll
    for (int i = 0; i < 10; i++) {
        const int idx = i * 256 + tid;
        const int t = idx >> 9;            // constant per i (= i>>1)
        const int rem = idx & 511;
        const int row = rem >> 2;
        const int seg = rem & 3;
        cp_async16(bufbase + t * TILEB + row * (AST * 2) + seg * 16,
                   gs[t] + (size_t)row * D_MODEL + c * KC + seg * 8);
    }
    asm volatile("cp.async.commit_group;\n" ::: "memory");
}

__global__ __launch_bounds__(256, 1) void gemm_qkv(
        const float* __restrict__ bq, const float* __restrict__ bk,
        const float* __restrict__ bv)
{
    extern __shared__ char smem[];
    const uint32_t sb = smem_u32(smem);
    const int tid = threadIdx.x;
    const int wid = tid >> 5, lane = tid & 31;
    const int wy = wid & 3, wx = wid >> 2;
    const int rowBase = blockIdx.y * 128;
    const int colBase = blockIdx.x * 128;

    const __half* gs[5];
    gs[0] = g_xh + (size_t)rowBase * D_MODEL;
    gs[1] = g_xl + (size_t)rowBase * D_MODEL;
#pragma unroll
    for (int z = 0; z < 3; z++)
        gs[2 + z] = g_Wt + (size_t)z * D_MODEL * D_MODEL + (size_t)colBase * D_MODEL;

    const uint32_t buf0 = sb, buf1 = sb + QSTAGE;

    float acc[3][2][8][4];
#pragma unroll
    for (int z = 0; z < 3; z++)
#pragma unroll
        for (int mt = 0; mt < 2; mt++)
#pragma unroll
            for (int nt = 0; nt < 8; nt++)
#pragma unroll
                for (int j = 0; j < 4; j++) acc[z][mt][nt][j] = 0.f;

    load_chunk_qkv(buf0, 0, tid, gs);
    load_chunk_qkv(buf1, 1, tid, gs);

    const int arow = (lane & 7) + ((lane >> 3) & 1) * 8;
    const int acol = (lane >> 4) * 8;
    const int brow = (lane & 7) + (lane >> 4) * 8;
    const int bcol = ((lane >> 3) & 1) * 8;

    for (int c = 0; c < NKC; c++) {
        const int b = c & 1;
        if (c < NKC - 1) asm volatile("cp.async.wait_group 1;\n" ::: "memory");
        else             asm volatile("cp.async.wait_group 0;\n" ::: "memory");
        __syncthreads();

        const uint32_t base = b ? buf1 : buf0;

#pragma unroll
        for (int ks = 0; ks < 2; ks++) {
            uint32_t ah[2][4], al[2][4];
#pragma unroll
            for (int mt = 0; mt < 2; mt++) {
                const uint32_t off = (uint32_t)(wy * 32 + mt * 16 + arow) * (AST * 2)
                                   + (uint32_t)(ks * 16 + acol) * 2;
                ldmat4(ah[mt], base + off);
                ldmat4(al[mt], base + TILEB + off);
            }
#pragma unroll
            for (int z = 0; z < 3; z++) {
#pragma unroll
                for (int np = 0; np < 4; np++) {
                    uint32_t bw[4];
                    const uint32_t off = (uint32_t)(wx * 64 + np * 16 + brow) * (AST * 2)
                                       + (uint32_t)(ks * 16 + bcol) * 2;
                    ldmat4(bw, base + (2 + z) * TILEB + off);
#pragma unroll
                    for (int mt = 0; mt < 2; mt++) {
                        mma_fp(acc[z][mt][np * 2],     ah[mt], &bw[0]);
                        mma_fp(acc[z][mt][np * 2 + 1], ah[mt], &bw[2]);
                        mma_fp(acc[z][mt][np * 2],     al[mt], &bw[0]);
                        mma_fp(acc[z][mt][np * 2 + 1], al[mt], &bw[2]);
                    }
                }
            }
        }
        __syncthreads();
        if (c + 2 < NKC)
            load_chunk_qkv(b ? buf1 : buf0, c + 2, tid, gs);
    }

    // epilogue: Q split-fp16, K/V single fp16
#pragma unroll
    for (int z = 0; z < 3; z++) {
        const float* bias = (z == 0) ? bq : (z == 1) ? bk : bv;
        __half* dH = (z == 0) ? g_Qh : (z == 1) ? g_Kh : g_Vh;
        const float sc = (z == 0) ? QSCALE : 1.0f;
#pragma unroll
        for (int mt = 0; mt < 2; mt++) {
#pragma unroll
            for (int nt = 0; nt < 8; nt++) {
                const int col0 = colBase + wx * 64 + nt * 8 + (lane & 3) * 2;
                const int hh = col0 >> 6, d0 = col0 & (D_HEAD - 1);
                const float b0 = bias[col0], b1 = bias[col0 + 1];
#pragma unroll
                for (int half_m = 0; half_m < 2; half_m++) {
                    const int row = rowBase + wy * 32 + mt * 16 + (lane >> 2) + half_m * 8;
                    const int bb = row >> 11, s = row & (SEQ - 1);
                    float v0 = (acc[z][mt][nt][half_m * 2]     + b0) * sc;
                    float v1 = (acc[z][mt][nt][half_m * 2 + 1] + b1) * sc;
                    const uint32_t hpair = pack2(v0, v1);
                    const size_t e = (((size_t)(bb * N_HEADS + hh)) * SEQ + s) * D_HEAD + d0;
                    *(uint32_t*)(dH + e) = hpair;
                    if (z == 0) {
                        float2 f = unpack2(hpair);
                        *(uint32_t*)(g_Ql + e) = pack2(v0 - f.x, v1 - f.y);
                    }
                }
            }
        }
    }
}

// ---------------- Wo GEMM: A split (2-pass), W single; 2 CTAs/SM ----------------
#define WSTAGE (3 * TILEB)             // Ah, Al, B = 30720 B

__device__ __forceinline__ void load_chunk_wo(uint32_t bufbase, int c, int tid,
        const __half* g0, const __half* g1, const __half* g2)
{
    const __half* gs[3] = {g0, g1, g2};
#pragma unroll
    for (int i = 0; i < 6; i++) {
        const int idx = i * 256 + tid;
        const int t = idx >> 9;
        const int rem = idx & 511;
        const int row = rem >> 2;
        const int seg = rem & 3;
        cp_async16(bufbase + t * TILEB + row * (AST * 2) + seg * 16,
                   gs[t] + (size_t)row * D_MODEL + c * KC + seg * 8);
    }
    asm volatile("cp.async.commit_group;\n" ::: "memory");
}

__global__ __launch_bounds__(256, 2) void gemm_wo(float* __restrict__ out)
{
    extern __shared__ char smem[];
    const uint32_t sb = smem_u32(smem);
    const int tid = threadIdx.x;
    const int wid = tid >> 5, lane = tid & 31;
    const int wy = wid & 3, wx = wid >> 2;
    const int rowBase = blockIdx.y * 128;
    const int colBase = blockIdx.x * 128;

    const __half* Ah = g_Ah + (size_t)rowBase * D_MODEL;
    const __half* Al = g_Al + (size_t)rowBase * D_MODEL;
    const __half* Bw = g_Wt + (size_t)3 * D_MODEL * D_MODEL + (size_t)colBase * D_MODEL;

    const uint32_t buf0 = sb, buf1 = sb + WSTAGE;

    float acc[2][8][4];
#pragma unroll
    for (int mt = 0; mt < 2; mt++)
#pragma unroll
        for (int nt = 0; nt < 8; nt++)
#pragma unroll
            for (int j = 0; j < 4; j++) acc[mt][nt][j] = 0.f;

    load_chunk_wo(buf0, 0, tid, Ah, Al, Bw);
    load_chunk_wo(buf1, 1, tid, Ah, Al, Bw);

    const int arow = (lane & 7) + ((lane >> 3) & 1) * 8;
    const int acol = (lane >> 4) * 8;
    const int brow = (lane & 7) + (lane >> 4) * 8;
    const int bcol = ((lane >> 3) & 1) * 8;

    for (int c = 0; c < NKC; c++) {
        const int b = c & 1;
        if (c < NKC - 1) asm volatile("cp.async.wait_group 1;\n" ::: "memory");
        else             asm volatile("cp.async.wait_group 0;\n" ::: "memory");
        __syncthreads();

        const uint32_t base = b ? buf1 : buf0;
        const uint32_t aHs = base, aLs = base + TILEB, bWs = base + 2 * TILEB;

#pragma unroll
        for (int ks = 0; ks < 2; ks++) {
            uint32_t ah[2][4], al[2][4];
#pragma unroll
            for (int mt = 0; mt < 2; mt++) {
                const uint32_t off = (uint32_t)(wy * 32 + mt * 16 + arow) * (AST * 2)
                                   + (uint32_t)(ks * 16 + acol) * 2;
                ldmat4(ah[mt], aHs + off);
                ldmat4(al[mt], aLs + off);
            }
#pragma unroll
            for (int np = 0; np < 4; np++) {
                uint32_t bw[4];
                const uint32_t off = (uint32_t)(wx * 64 + np * 16 + brow) * (AST * 2)
                                   + (uint32_t)(ks * 16 + bcol) * 2;
                ldmat4(bw, bWs + off);
#pragma unroll
                for (int mt = 0; mt < 2; mt++) {
                    mma_fp(acc[mt][np * 2],     ah[mt], &bw[0]);
                    mma_fp(acc[mt][np * 2 + 1], ah[mt], &bw[2]);
                    mma_fp(acc[mt][np * 2],     al[mt], &bw[0]);
                    mma_fp(acc[mt][np * 2 + 1], al[mt], &bw[2]);
                }
            }
        }
        __syncthreads();
        if (c + 2 < NKC)
            load_chunk_wo(b ? buf1 : buf0, c + 2, tid, Ah, Al, Bw);
    }

#pragma unroll
    for (int mt = 0; mt < 2; mt++)
#pragma unroll
        for (int nt = 0; nt < 8; nt++)
#pragma unroll
            for (int j = 0; j < 4; j++) {
                const int row = rowBase + wy * 32 + mt * 16 + (lane >> 2) + (j >> 1) * 8;
                const int col = colBase + wx * 64 + nt * 8 + (lane & 3) * 2 + (j & 1);
                out[(size_t)row * D_MODEL + col] = acc[mt][nt][j];
            }
}

// ---------------- tensor-core flash attention (BK=128, LPT scheduling) ----------------
#define FBK    128
#define FST    72
#define QTILE  (128 * FST)             // halves
#define KTILE  (128 * FST)             // halves
#define KVSTG  (2 * KTILE)             // Kh, Vh

__device__ __forceinline__ void load_kv(__half* stagep, int kb, int tid,
        const __half* gK, const __half* gV)
{
#pragma unroll
    for (int i = 0; i < 8; i++) {
        const int idx = i * 256 + tid;
        const int t = idx >> 10;
        const int rem = idx & 1023;
        const int row = rem >> 3;
        const int seg = rem & 7;
        const __half* g = (t == 0 ? gK : gV) + (size_t)(kb + row) * D_HEAD + seg * 8;
        cp_async16(smem_u32(stagep + t * KTILE + row * FST + seg * 8), g);
    }
    asm volatile("cp.async.commit_group;\n" ::: "memory");
}

__global__ __launch_bounds__(256, 1) void flash_mma()
{
    extern __shared__ __half fsm[];
    const int tid = threadIdx.x;
    const int wid = tid >> 5, lane = tid & 31;
    // LPT: heavy (late-causal) q-tiles scheduled first
    const int qt = gridDim.x - 1 - blockIdx.x;
    const int h = blockIdx.y, b = blockIdx.z;
    const int bh = b * N_HEADS + h;
    const int qBase = qt * 128;
    const size_t gbase = (size_t)bh * SEQ * D_HEAD;

    const __half* gQh = g_Qh + gbase;
    const __half* gQl = g_Ql + gbase;
    const __half* gK  = g_Kh + gbase;
    const __half* gV  = g_Vh + gbase;

    __half* sQh = fsm;
    __half* sQl = fsm + QTILE;
    __half* stage0 = fsm + 2 * QTILE;
    __half* stage1 = stage0 + KVSTG;

    // Q tile load (group 0)
#pragma unroll
    for (int i = 0; i < 8; i++) {
        const int idx = i * 256 + tid;
        const int t = idx >> 10;
        const int rem = idx & 1023;
        const int row = rem >> 3;
        const int seg = rem & 7;
        const __half* g = (t ? gQl : gQh) + (size_t)(qBase + row) * D_HEAD + seg * 8;
        cp_async16(smem_u32((t ? sQl : sQh) + row * FST + seg * 8), g);
    }
    asm volatile("cp.async.commit_group;\n" ::: "memory");

    const int nkt = qt + 1;
    load_kv(stage0, 0, tid, gK, gV);
    load_kv(stage1, FBK, tid, gK, gV);

    const int arow = (lane & 7) + ((lane >> 3) & 1) * 8;
    const int acol = (lane >> 4) * 8;
    const int brow = (lane & 7) + (lane >> 4) * 8;
    const int bcol = ((lane >> 3) & 1) * 8;
    const int trow = (lane & 7) + ((lane >> 3) & 1) * 8;
    const int tcol = (lane >> 4) * 8;

    uint32_t qh[4][4], ql[4][4];
    float o[8][4];
#pragma unroll
    for (int nb = 0; nb < 8; nb++)
#pragma unroll
        for (int j = 0; j < 4; j++) o[nb][j] = 0.f;
    float m0 = -1e30f, m1 = -1e30f, l0 = 0.f, l1 = 0.f;

    const int row0 = qBase + wid * 16 + (lane >> 2);
    const int row1 = row0 + 8;

    for (int jt = 0; jt < nkt; jt++) {
        __half* stg = (jt & 1) ? stage1 : stage0;
        if (jt < nkt - 1) asm volatile("cp.async.wait_group 1;\n" ::: "memory");
        else              asm volatile("cp.async.wait_group 0;\n" ::: "memory");
        __syncthreads();

        if (jt == 0) {
#pragma unroll
            for (int kk = 0; kk < 4; kk++) {
                const uint32_t off = (uint32_t)(wid * 16 + arow) * (FST * 2)
                                   + (uint32_t)(kk * 16 + acol) * 2;
                ldmat4(qh[kk], smem_u32(sQh) + off);
                ldmat4(ql[kk], smem_u32(sQl) + off);
            }
        }

        const uint32_t sK = smem_u32(stg);
        const uint32_t sV = sK + KTILE * 2;

        float s[16][4];
#pragma unroll
        for (int nb = 0; nb < 16; nb++)
#pragma unroll
            for (int j = 0; j < 4; j++) s[nb][j] = 0.f;

        // ---- S = Q K^T : 2 passes (qh*k + ql*k) ----
#pragma unroll
        for (int kk = 0; kk < 4; kk++) {
#pragma unroll
            for (int np = 0; np < 8; np++) {
                uint32_t bk4[4];
                const uint32_t off = (uint32_t)(np * 16 + brow) * (FST * 2)
                                   + (uint32_t)(kk * 16 + bcol) * 2;
                ldmat4(bk4, sK + off);
                mma_fp(s[np * 2],     qh[kk], &bk4[0]);
                mma_fp(s[np * 2 + 1], qh[kk], &bk4[2]);
                mma_fp(s[np * 2],     ql[kk], &bk4[0]);
                mma_fp(s[np * 2 + 1], ql[kk], &bk4[2]);
            }
        }

        // ---- causal mask (diagonal tile only) ----
        if (jt == qt) {
            const int kb = jt * FBK;
#pragma unroll
            for (int nb = 0; nb < 16; nb++) {
#pragma unroll
                for (int j = 0; j < 4; j++) {
                    const int key = kb + nb * 8 + (lane & 3) * 2 + (j & 1);
                    const int qr = (j < 2) ? row0 : row1;
                    if (key > qr) s[nb][j] = -1e30f;
                }
            }
        }

        // ---- online softmax (exp2 domain) ----
        float mx0 = -1e30f, mx1 = -1e30f;
#pragma unroll
        for (int nb = 0; nb < 16; nb++) {
            mx0 = fmaxf(mx0, fmaxf(s[nb][0], s[nb][1]));
            mx1 = fmaxf(mx1, fmaxf(s[nb][2], s[nb][3]));
        }
        mx0 = fmaxf(mx0, __shfl_xor_sync(0xffffffffu, mx0, 1));
        mx0 = fmaxf(mx0, __shfl_xor_sync(0xffffffffu, mx0, 2));
        mx1 = fmaxf(mx1, __shfl_xor_sync(0xffffffffu, mx1, 1));
        mx1 = fmaxf(mx1, __shfl_xor_sync(0xffffffffu, mx1, 2));
        const float mn0 = fmaxf(m0, mx0), mn1 = fmaxf(m1, mx1);
        const float c0 = fexp2(m0 - mn0), c1 = fexp2(m1 - mn1);
        m0 = mn0; m1 = mn1;

        float sum0 = 0.f, sum1 = 0.f;
#pragma unroll
        for (int nb = 0; nb < 16; nb++) {
            s[nb][0] = fexp2(s[nb][0] - m0); sum0 += s[nb][0];
            s[nb][1] = fexp2(s[nb][1] - m0); sum0 += s[nb][1];
            s[nb][2] = fexp2(s[nb][2] - m1); sum1 += s[nb][2];
            s[nb][3] = fexp2(s[nb][3] - m1); sum1 += s[nb][3];
        }
        sum0 += __shfl_xor_sync(0xffffffffu, sum0, 1);
        sum0 += __shfl_xor_sync(0xffffffffu, sum0, 2);
        sum1 += __shfl_xor_sync(0xffffffffu, sum1, 1);
        sum1 += __shfl_xor_sync(0xffffffffu, sum1, 2);
        l0 = l0 * c0 + sum0;
        l1 = l1 * c1 + sum1;

#pragma unroll
        for (int nb = 0; nb < 8; nb++) {
            o[nb][0] *= c0; o[nb][1] *= c0;
            o[nb][2] *= c1; o[nb][3] *= c1;
        }

        // ---- O += P V (P split, V single) ----
#pragma unroll
        for (int kk = 0; kk < 8; kk++) {
            uint32_t aH[4], aL[4];
            aH[0] = pack2(s[2 * kk][0], s[2 * kk][1]);
            aH[1] = pack2(s[2 * kk][2], s[2 * kk][3]);
            aH[2] = pack2(s[2 * kk + 1][0], s[2 * kk + 1][1]);
            aH[3] = pack2(s[2 * kk + 1][2], s[2 * kk + 1][3]);
#pragma unroll
            for (int i = 0; i < 4; i++) {
                const int nb = 2 * kk + (i >> 1);
                const int j0 = (i & 1) * 2;
                float2 f = unpack2(aH[i]);
                aL[i] = pack2(s[nb][j0] - f.x, s[nb][j0 + 1] - f.y);
            }
#pragma unroll
            for (int np = 0; np < 4; np++) {
                uint32_t bv[4];
                const uint32_t off = (uint32_t)(kk * 16 + trow) * (FST * 2)
                                   + (uint32_t)(np * 16 + tcol) * 2;
                ldmat4t(bv, sV + off);
                mma_fp(o[np * 2],     aH, &bv[0]);
                mma_fp(o[np * 2 + 1], aH, &bv[2]);
                mma_fp(o[np * 2],     aL, &bv[0]);
                mma_fp(o[np * 2 + 1], aL, &bv[2]);
            }
        }

        __syncthreads();
        if (jt + 2 < nkt)
            load_kv(stg, (jt + 2) * FBK, tid, gK, gV);
    }

    // ---- epilogue: normalize, split-fp16, write g_Ah/g_Al ----
    const float inv0 = 1.f / l0, inv1 = 1.f / l1;
#pragma unroll
    for (int nb = 0; nb < 8; nb++) {
        const int d0 = h * D_HEAD + nb * 8 + (lane & 3) * 2;
#pragma unroll
        for (int half_m = 0; half_m < 2; half_m++) {
            const int row = half_m ? row1 : row0;
            const float inv = half_m ? inv1 : inv0;
            const float v0 = o[nb][half_m * 2] * inv;
            const float v1 = o[nb][half_m * 2 + 1] * inv;
            const uint32_t uh = pack2(v0, v1);
            float2 f = unpack2(uh);
            const uint32_t ul = pack2(v0 - f.x, v1 - f.y);
            const size_t e = (size_t)(b * SEQ + row) * D_MODEL + d0;
            *(uint32_t*)(g_Ah + e) = uh;
            *(uint32_t*)(g_Al + e) = ul;
        }
    }
}

// ---------------- launch ----------------
extern "C" void kernel_launch(void* const* d_in, const int* in_sizes, int n_in,
                              void* d_out, int out_size)
{
    const float* x  = (const float*)d_in[0];
    const float* Wq = (const float*)d_in[1];
    const float* bq = (const float*)d_in[2];
    const float* Wk = (const float*)d_in[3];
    const float* bk = (const float*)d_in[4];
    const float* Wv = (const float*)d_in[5];
    const float* bv = (const float*)d_in[6];
    const float* Wo = (const float*)d_in[7];
    float* out = (float*)d_out;

    const int qkvSmem = 2 * QSTAGE;                                   // 102400
    cudaFuncSetAttribute(gemm_qkv, cudaFuncAttributeMaxDynamicSharedMemorySize, qkvSmem);
    const int woSmem = 2 * WSTAGE;                                    // 61440
    cudaFuncSetAttribute(gemm_wo, cudaFuncAttributeMaxDynamicSharedMemorySize, woSmem);
    const int flashSmem = (2 * QTILE + 2 * KVSTG) * (int)sizeof(__half);  // 110592
    cudaFuncSetAttribute(flash_mma, cudaFuncAttributeMaxDynamicSharedMemorySize, flashSmem);

    cvt_rm<<<M_ROWS * D_MODEL / 4 / 256, 256>>>(x);
    cvt_wt<<<dim3(D_MODEL / 32, D_MODEL / 32, 4), 256>>>(Wq, Wk, Wv, Wo);
    gemm_qkv<<<dim3(D_MODEL / 128, M_ROWS / 128), 256, qkvSmem>>>(bq, bk, bv);
    flash_mma<<<dim3(SEQ / 128, N_HEADS, BATCH), 256, flashSmem>>>();
    gemm_wo<<<dim3(D_MODEL / 128, M_ROWS / 128), 256, woSmem>>>(out);
}

// round 16
// speedup vs baseline: 1.8163x; 1.1331x over previous
#include <cuda_runtime.h>
#include <cuda_fp16.h>
#include <cstdint>

#define D_MODEL 1024
#define N_HEADS 16
#define D_HEAD  64
#define BATCH   2
#define SEQ     2048
#define M_ROWS  (BATCH * SEQ)      // 4096

// Q pre-scale: 1/sqrt(Dh) * log2(e)  (softmax computed in exp2 domain)
#define QSCALE 0.1803368801111204f

// ---------------- scratch (no allocations allowed) ----------------
__device__ __half g_Qh[(size_t)BATCH * N_HEADS * SEQ * D_HEAD];
__device__ __half g_Ql[(size_t)BATCH * N_HEADS * SEQ * D_HEAD];
__device__ __half g_Kh[(size_t)BATCH * N_HEADS * SEQ * D_HEAD];   // single fp16 K
__device__ __half g_Vh[(size_t)BATCH * N_HEADS * SEQ * D_HEAD];   // single fp16 V

__device__ __half g_xh[(size_t)M_ROWS * D_MODEL];                 // x split fp16
__device__ __half g_xl[(size_t)M_ROWS * D_MODEL];
__device__ __half g_Ah[(size_t)M_ROWS * D_MODEL];                 // attn out split fp16
__device__ __half g_Al[(size_t)M_ROWS * D_MODEL];
__device__ __half g_Wt[(size_t)4 * D_MODEL * D_MODEL];            // W^T single fp16 [4][n][k]

// ---------------- helpers ----------------
__device__ __forceinline__ uint32_t smem_u32(const void* p) {
    uint32_t a;
    asm("{ .reg .u64 t; cvta.to.shared.u64 t, %1; cvt.u32.u64 %0, t; }" : "=r"(a) : "l"(p));
    return a;
}
__device__ __forceinline__ void cp_async16(uint32_t sa, const void* g) {
    asm volatile("cp.async.cg.shared.global [%0], [%1], 16;\n" :: "r"(sa), "l"(g));
}
__device__ __forceinline__ void ldmat4(uint32_t* r, uint32_t addr) {
    asm volatile("ldmatrix.sync.aligned.m8n8.x4.shared.b16 {%0,%1,%2,%3}, [%4];"
        : "=r"(r[0]), "=r"(r[1]), "=r"(r[2]), "=r"(r[3]) : "r"(addr));
}
__device__ __forceinline__ void ldmat4t(uint32_t* r, uint32_t addr) {
    asm volatile("ldmatrix.sync.aligned.m8n8.x4.trans.shared.b16 {%0,%1,%2,%3}, [%4];"
        : "=r"(r[0]), "=r"(r[1]), "=r"(r[2]), "=r"(r[3]) : "r"(addr));
}
__device__ __forceinline__ void mma_fp(float* c, const uint32_t* a, const uint32_t* b) {
    asm volatile("mma.sync.aligned.m16n8k16.row.col.f32.f16.f16.f32 "
        "{%0,%1,%2,%3}, {%4,%5,%6,%7}, {%8,%9}, {%0,%1,%2,%3};"
        : "+f"(c[0]), "+f"(c[1]), "+f"(c[2]), "+f"(c[3])
        : "r"(a[0]), "r"(a[1]), "r"(a[2]), "r"(a[3]), "r"(b[0]), "r"(b[1]));
}
__device__ __forceinline__ float fexp2(float x) {
    float r; asm("ex2.approx.f32 %0, %1;" : "=f"(r) : "f"(x)); return r;
}
__device__ __forceinline__ uint32_t ex2h2(uint32_t a) {
    uint32_t r; asm("ex2.approx.f16x2 %0, %1;" : "=r"(r) : "r"(a)); return r;
}
__device__ __forceinline__ uint32_t pack2(float x, float y) {
    uint32_t r; asm("cvt.rn.f16x2.f32 %0, %1, %2;" : "=r"(r) : "f"(y), "f"(x)); return r;
}
__device__ __forceinline__ float2 unpack2(uint32_t u) {
    __half2 h; *reinterpret_cast<uint32_t*>(&h) = u;
    return __half22float2(h);
}

// ---------------- conversion kernels ----------------
__global__ __launch_bounds__(256) void cvt_rm(const float* __restrict__ src)
{
    const size_t i4 = (size_t)blockIdx.x * blockDim.x + threadIdx.x;
    if (i4 < (size_t)M_ROWS * D_MODEL / 4) {
        float4 v = ((const float4*)src)[i4];
        float vv[4] = {v.x, v.y, v.z, v.w};
#pragma unroll
        for (int j = 0; j < 4; j++) {
            __half h = __float2half_rn(vv[j]);
            g_xh[i4 * 4 + j] = h;
            g_xl[i4 * 4 + j] = __float2half_rn(vv[j] - __half2float(h));
        }
    }
}

__global__ __launch_bounds__(256) void cvt_wt(const float* __restrict__ Wq,
                                              const float* __restrict__ Wk,
                                              const float* __restrict__ Wv,
                                              const float* __restrict__ Wo)
{
    __shared__ float t[32][33];
    const int z = blockIdx.z;
    const float* W = (z == 0) ? Wq : (z == 1) ? Wk : (z == 2) ? Wv : Wo;
    __half* dst = g_Wt + (size_t)z * D_MODEL * D_MODEL;
    const int n0 = blockIdx.x * 32, k0 = blockIdx.y * 32;
    const int tx = threadIdx.x & 31, ty = threadIdx.x >> 5;
    for (int r = ty; r < 32; r += 8)
        t[r][tx] = W[(size_t)(k0 + r) * D_MODEL + n0 + tx];
    __syncthreads();
    for (int r = ty; r < 32; r += 8)
        dst[(size_t)(n0 + r) * D_MODEL + k0 + tx] = __float2half_rn(t[tx][r]);
}

// ---------------- fused QKV GEMM: KC=64, A split (2-pass), W single ----------------
#define AST2   72
#define TILEB2 (128 * AST2 * 2)        // 18432 B per 128x64 fp16 tile
#define KC2    64
#define NKC2   (D_MODEL / KC2)         // 16 chunks
#define QSTAGE (5 * TILEB2)            // 92160 B : [Ah, Al, BQ, BK, BV]

__device__ __forceinline__ void load_chunk_qkv(uint32_t bufbase, int c, int tid,
        const __half* const* gs)
{
#pragma unroll
    for (int i = 0; i < 20; i++) {
        const int idx = i * 256 + tid;
        const int t = idx >> 10;           // tile 0..4 (constant per i)
        const int rem = idx & 1023;
        const int row = rem >> 3;
        const int seg = rem & 7;
        cp_async16(bufbase + t * TILEB2 + row * (AST2 * 2) + seg * 16,
                   gs[t] + (size_t)row * D_MODEL + c * KC2 + seg * 8);
    }
    asm volatile("cp.async.commit_group;\n" ::: "memory");
}

__global__ __launch_bounds__(256, 1) void gemm_qkv(
        const float* __restrict__ bq, const float* __restrict__ bk,
        const float* __restrict__ bv)
{
    extern __shared__ char smem[];
    const uint32_t sb = smem_u32(smem);
    const int tid = threadIdx.x;
    const int wid = tid >> 5, lane = tid & 31;
    const int wy = wid & 3, wx = wid >> 2;
    const int rowBase = blockIdx.y * 128;
    const int colBase = blockIdx.x * 128;

    const __half* gs[5];
    gs[0] = g_xh + (size_t)rowBase * D_MODEL;
    gs[1] = g_xl + (size_t)rowBase * D_MODEL;
#pragma unroll
    for (int z = 0; z < 3; z++)
        gs[2 + z] = g_Wt + (size_t)z * D_MODEL * D_MODEL + (size_t)colBase * D_MODEL;

    const uint32_t buf0 = sb, buf1 = sb + QSTAGE;

    float acc[3][2][8][4];
#pragma unroll
    for (int z = 0; z < 3; z++)
#pragma unroll
        for (int mt = 0; mt < 2; mt++)
#pragma unroll
            for (int nt = 0; nt < 8; nt++)
#pragma unroll
                for (int j = 0; j < 4; j++) acc[z][mt][nt][j] = 0.f;

    load_chunk_qkv(buf0, 0, tid, gs);
    load_chunk_qkv(buf1, 1, tid, gs);

    const int arow = (lane & 7) + ((lane >> 3) & 1) * 8;
    const int acol = (lane >> 4) * 8;
    const int brow = (lane & 7) + (lane >> 4) * 8;
    const int bcol = ((lane >> 3) & 1) * 8;

    for (int c = 0; c < NKC2; c++) {
        const int b = c & 1;
        if (c < NKC2 - 1) asm volatile("cp.async.wait_group 1;\n" ::: "memory");
        else              asm volatile("cp.async.wait_group 0;\n" ::: "memory");
        __syncthreads();

        const uint32_t base = b ? buf1 : buf0;

#pragma unroll
        for (int ks = 0; ks < 4; ks++) {
            uint32_t ah[2][4], al[2][4];
#pragma unroll
            for (int mt = 0; mt < 2; mt++) {
                const uint32_t off = (uint32_t)(wy * 32 + mt * 16 + arow) * (AST2 * 2)
                                   + (uint32_t)(ks * 16 + acol) * 2;
                ldmat4(ah[mt], base + off);
                ldmat4(al[mt], base + TILEB2 + off);
            }
#pragma unroll
            for (int z = 0; z < 3; z++) {
#pragma unroll
                for (int np = 0; np < 4; np++) {
                    uint32_t bw[4];
                    const uint32_t off = (uint32_t)(wx * 64 + np * 16 + brow) * (AST2 * 2)
                                       + (uint32_t)(ks * 16 + bcol) * 2;
                    ldmat4(bw, base + (2 + z) * TILEB2 + off);
#pragma unroll
                    for (int mt = 0; mt < 2; mt++) {
                        mma_fp(acc[z][mt][np * 2],     ah[mt], &bw[0]);
                        mma_fp(acc[z][mt][np * 2 + 1], ah[mt], &bw[2]);
                        mma_fp(acc[z][mt][np * 2],     al[mt], &bw[0]);
                        mma_fp(acc[z][mt][np * 2 + 1], al[mt], &bw[2]);
                    }
                }
            }
        }
        __syncthreads();
        if (c + 2 < NKC2)
            load_chunk_qkv(b ? buf1 : buf0, c + 2, tid, gs);
    }

    // epilogue: Q split-fp16, K/V single fp16
#pragma unroll
    for (int z = 0; z < 3; z++) {
        const float* bias = (z == 0) ? bq : (z == 1) ? bk : bv;
        __half* dH = (z == 0) ? g_Qh : (z == 1) ? g_Kh : g_Vh;
        const float sc = (z == 0) ? QSCALE : 1.0f;
#pragma unroll
        for (int mt = 0; mt < 2; mt++) {
#pragma unroll
            for (int nt = 0; nt < 8; nt++) {
                const int col0 = colBase + wx * 64 + nt * 8 + (lane & 3) * 2;
                const int hh = col0 >> 6, d0 = col0 & (D_HEAD - 1);
                const float b0 = bias[col0], b1 = bias[col0 + 1];
#pragma unroll
                for (int half_m = 0; half_m < 2; half_m++) {
                    const int row = rowBase + wy * 32 + mt * 16 + (lane >> 2) + half_m * 8;
                    const int bb = row >> 11, s = row & (SEQ - 1);
                    float v0 = (acc[z][mt][nt][half_m * 2]     + b0) * sc;
                    float v1 = (acc[z][mt][nt][half_m * 2 + 1] + b1) * sc;
                    const uint32_t hpair = pack2(v0, v1);
                    const size_t e = (((size_t)(bb * N_HEADS + hh)) * SEQ + s) * D_HEAD + d0;
                    *(uint32_t*)(dH + e) = hpair;
                    if (z == 0) {
                        float2 f = unpack2(hpair);
                        *(uint32_t*)(g_Ql + e) = pack2(v0 - f.x, v1 - f.y);
                    }
                }
            }
        }
    }
}

// ---------------- Wo GEMM: A split (2-pass), W single; 2 CTAs/SM ----------------
#define AST   40
#define TILEB (128 * AST * 2)          // 10240 B per 128x32 fp16 tile
#define KC    32
#define NKC   (D_MODEL / KC)           // 32 chunks
#define WSTAGE (3 * TILEB)             // Ah, Al, B = 30720 B

__device__ __forceinline__ void load_chunk_wo(uint32_t bufbase, int c, int tid,
        const __half* g0, const __half* g1, const __half* g2)
{
    const __half* gs[3] = {g0, g1, g2};
#pragma unroll
    for (int i = 0; i < 6; i++) {
        const int idx = i * 256 + tid;
        const int t = idx >> 9;
        const int rem = idx & 511;
        const int row = rem >> 2;
        const int seg = rem & 3;
        cp_async16(bufbase + t * TILEB + row * (AST * 2) + seg * 16,
                   gs[t] + (size_t)row * D_MODEL + c * KC + seg * 8);
    }
    asm volatile("cp.async.commit_group;\n" ::: "memory");
}

__global__ __launch_bounds__(256, 2) void gemm_wo(float* __restrict__ out)
{
    extern __shared__ char smem[];
    const uint32_t sb = smem_u32(smem);
    const int tid = threadIdx.x;
    const int wid = tid >> 5, lane = tid & 31;
    const int wy = wid & 3, wx = wid >> 2;
    const int rowBase = blockIdx.y * 128;
    const int colBase = blockIdx.x * 128;

    const __half* Ah = g_Ah + (size_t)rowBase * D_MODEL;
    const __half* Al = g_Al + (size_t)rowBase * D_MODEL;
    const __half* Bw = g_Wt + (size_t)3 * D_MODEL * D_MODEL + (size_t)colBase * D_MODEL;

    const uint32_t buf0 = sb, buf1 = sb + WSTAGE;

    float acc[2][8][4];
#pragma unroll
    for (int mt = 0; mt < 2; mt++)
#pragma unroll
        for (int nt = 0; nt < 8; nt++)
#pragma unroll
            for (int j = 0; j < 4; j++) acc[mt][nt][j] = 0.f;

    load_chunk_wo(buf0, 0, tid, Ah, Al, Bw);
    load_chunk_wo(buf1, 1, tid, Ah, Al, Bw);

    const int arow = (lane & 7) + ((lane >> 3) & 1) * 8;
    const int acol = (lane >> 4) * 8;
    const int brow = (lane & 7) + (lane >> 4) * 8;
    const int bcol = ((lane >> 3) & 1) * 8;

    for (int c = 0; c < NKC; c++) {
        const int b = c & 1;
        if (c < NKC - 1) asm volatile("cp.async.wait_group 1;\n" ::: "memory");
        else             asm volatile("cp.async.wait_group 0;\n" ::: "memory");
        __syncthreads();

        const uint32_t base = b ? buf1 : buf0;
        const uint32_t aHs = base, aLs = base + TILEB, bWs = base + 2 * TILEB;

#pragma unroll
        for (int ks = 0; ks < 2; ks++) {
            uint32_t ah[2][4], al[2][4];
#pragma unroll
            for (int mt = 0; mt < 2; mt++) {
                const uint32_t off = (uint32_t)(wy * 32 + mt * 16 + arow) * (AST * 2)
                                   + (uint32_t)(ks * 16 + acol) * 2;
                ldmat4(ah[mt], aHs + off);
                ldmat4(al[mt], aLs + off);
            }
#pragma unroll
            for (int np = 0; np < 4; np++) {
                uint32_t bw[4];
                const uint32_t off = (uint32_t)(wx * 64 + np * 16 + brow) * (AST * 2)
                                   + (uint32_t)(ks * 16 + bcol) * 2;
                ldmat4(bw, bWs + off);
#pragma unroll
                for (int mt = 0; mt < 2; mt++) {
                    mma_fp(acc[mt][np * 2],     ah[mt], &bw[0]);
                    mma_fp(acc[mt][np * 2 + 1], ah[mt], &bw[2]);
                    mma_fp(acc[mt][np * 2],     al[mt], &bw[0]);
                    mma_fp(acc[mt][np * 2 + 1], al[mt], &bw[2]);
                }
            }
        }
        __syncthreads();
        if (c + 2 < NKC)
            load_chunk_wo(b ? buf1 : buf0, c + 2, tid, Ah, Al, Bw);
    }

#pragma unroll
    for (int mt = 0; mt < 2; mt++)
#pragma unroll
        for (int nt = 0; nt < 8; nt++)
#pragma unroll
            for (int j = 0; j < 4; j++) {
                const int row = rowBase + wy * 32 + mt * 16 + (lane >> 2) + (j >> 1) * 8;
                const int col = colBase + wx * 64 + nt * 8 + (lane & 3) * 2 + (j & 1);
                out[(size_t)row * D_MODEL + col] = acc[mt][nt][j];
            }
}

// ---------------- tensor-core flash attention ----------------
// BK=128, LPT; softmax via ex2.f16x2; P single fp16; l via ones-MMA
#define FBK    128
#define FST    72
#define QTILE  (128 * FST)             // halves
#define KTILE  (128 * FST)             // halves
#define KVSTG  (2 * KTILE)             // Kh, Vh

__device__ __forceinline__ void load_kv(__half* stagep, int kb, int tid,
        const __half* gK, const __half* gV)
{
#pragma unroll
    for (int i = 0; i < 8; i++) {
        const int idx = i * 256 + tid;
        const int t = idx >> 10;
        const int rem = idx & 1023;
        const int row = rem >> 3;
        const int seg = rem & 7;
        const __half* g = (t == 0 ? gK : gV) + (size_t)(kb + row) * D_HEAD + seg * 8;
        cp_async16(smem_u32(stagep + t * KTILE + row * FST + seg * 8), g);
    }
    asm volatile("cp.async.commit_group;\n" ::: "memory");
}

__global__ __launch_bounds__(256, 1) void flash_mma()
{
    extern __shared__ __half fsm[];
    const int tid = threadIdx.x;
    const int wid = tid >> 5, lane = tid & 31;
    const int qt = gridDim.x - 1 - blockIdx.x;   // LPT: heavy tiles first
    const int h = blockIdx.y, b = blockIdx.z;
    const int bh = b * N_HEADS + h;
    const int qBase = qt * 128;
    const size_t gbase = (size_t)bh * SEQ * D_HEAD;

    const __half* gQh = g_Qh + gbase;
    const __half* gQl = g_Ql + gbase;
    const __half* gK  = g_Kh + gbase;
    const __half* gV  = g_Vh + gbase;

    __half* sQh = fsm;
    __half* sQl = fsm + QTILE;
    __half* stage0 = fsm + 2 * QTILE;
    __half* stage1 = stage0 + KVSTG;

    // Q tile load (group 0)
#pragma unroll
    for (int i = 0; i < 8; i++) {
        const int idx = i * 256 + tid;
        const int t = idx >> 10;
        const int rem = idx & 1023;
        const int row = rem >> 3;
        const int seg = rem & 7;
        const __half* g = (t ? gQl : gQh) + (size_t)(qBase + row) * D_HEAD + seg * 8;
        cp_async16(smem_u32((t ? sQl : sQh) + row * FST + seg * 8), g);
    }
    asm volatile("cp.async.commit_group;\n" ::: "memory");

    const int nkt = qt + 1;
    load_kv(stage0, 0, tid, gK, gV);
    load_kv(stage1, FBK, tid, gK, gV);

    const int arow = (lane & 7) + ((lane >> 3) & 1) * 8;
    const int acol = (lane >> 4) * 8;
    const int brow = (lane & 7) + (lane >> 4) * 8;
    const int bcol = ((lane >> 3) & 1) * 8;
    const int trow = (lane & 7) + ((lane >> 3) & 1) * 8;
    const int tcol = (lane >> 4) * 8;

    uint32_t qh[4][4], ql[4][4];
    float o[8][4];
#pragma unroll
    for (int nb = 0; nb < 8; nb++)
#pragma unroll
        for (int j = 0; j < 4; j++) o[nb][j] = 0.f;
    float m0 = -1e30f, m1 = -1e30f, l0 = 0.f, l1 = 0.f;

    const int row0 = qBase + wid * 16 + (lane >> 2);
    const int row1 = row0 + 8;

    const uint32_t ones2 = 0x3C003C00u;          // half2(1.0, 1.0)
    uint32_t bones[2] = {ones2, ones2};

    for (int jt = 0; jt < nkt; jt++) {
        __half* stg = (jt & 1) ? stage1 : stage0;
        if (jt < nkt - 1) asm volatile("cp.async.wait_group 1;\n" ::: "memory");
        else              asm volatile("cp.async.wait_group 0;\n" ::: "memory");
        __syncthreads();

        if (jt == 0) {
#pragma unroll
            for (int kk = 0; kk < 4; kk++) {
                const uint32_t off = (uint32_t)(wid * 16 + arow) * (FST * 2)
                                   + (uint32_t)(kk * 16 + acol) * 2;
                ldmat4(qh[kk], smem_u32(sQh) + off);
                ldmat4(ql[kk], smem_u32(sQl) + off);
            }
        }

        const uint32_t sK = smem_u32(stg);
        const uint32_t sV = sK + KTILE * 2;

        float s[16][4];
#pragma unroll
        for (int nb = 0; nb < 16; nb++)
#pragma unroll
            for (int j = 0; j < 4; j++) s[nb][j] = 0.f;

        // ---- S = Q K^T : 2 passes (qh*k + ql*k) ----
#pragma unroll
        for (int kk = 0; kk < 4; kk++) {
#pragma unroll
            for (int np = 0; np < 8; np++) {
                uint32_t bk4[4];
                const uint32_t off = (uint32_t)(np * 16 + brow) * (FST * 2)
                                   + (uint32_t)(kk * 16 + bcol) * 2;
                ldmat4(bk4, sK + off);
                mma_fp(s[np * 2],     qh[kk], &bk4[0]);
                mma_fp(s[np * 2 + 1], qh[kk], &bk4[2]);
                mma_fp(s[np * 2],     ql[kk], &bk4[0]);
                mma_fp(s[np * 2 + 1], ql[kk], &bk4[2]);
            }
        }

        // ---- causal mask (diagonal tile only) ----
        if (jt == qt) {
            const int kb = jt * FBK;
#pragma unroll
            for (int nb = 0; nb < 16; nb++) {
#pragma unroll
                for (int j = 0; j < 4; j++) {
                    const int key = kb + nb * 8 + (lane & 3) * 2 + (j & 1);
                    const int qr = (j < 2) ? row0 : row1;
                    if (key > qr) s[nb][j] = -1e30f;
                }
            }
        }

        // ---- online softmax: max in fp32, exp in fp16x2 ----
        float mx0 = -1e30f, mx1 = -1e30f;
#pragma unroll
        for (int nb = 0; nb < 16; nb++) {
            mx0 = fmaxf(mx0, fmaxf(s[nb][0], s[nb][1]));
            mx1 = fmaxf(mx1, fmaxf(s[nb][2], s[nb][3]));
        }
        mx0 = fmaxf(mx0, __shfl_xor_sync(0xffffffffu, mx0, 1));
        mx0 = fmaxf(mx0, __shfl_xor_sync(0xffffffffu, mx0, 2));
        mx1 = fmaxf(mx1, __shfl_xor_sync(0xffffffffu, mx1, 1));
        mx1 = fmaxf(mx1, __shfl_xor_sync(0xffffffffu, mx1, 2));
        const float mn0 = fmaxf(m0, mx0), mn1 = fmaxf(m1, mx1);
        const float c0 = fexp2(m0 - mn0), c1 = fexp2(m1 - mn1);
        m0 = mn0; m1 = mn1;

        // p[nb][0] = half2 probs for row0 cols (j0,j1); p[nb][1] for row1 (j2,j3)
        uint32_t p[16][2];
#pragma unroll
        for (int nb = 0; nb < 16; nb++) {
            p[nb][0] = ex2h2(pack2(s[nb][0] - m0, s[nb][1] - m0));
            p[nb][1] = ex2h2(pack2(s[nb][2] - m1, s[nb][3] - m1));
        }

        // rescale O accumulator
#pragma unroll
        for (int nb = 0; nb < 8; nb++) {
            o[nb][0] *= c0; o[nb][1] *= c0;
            o[nb][2] *= c1; o[nb][3] *= c1;
        }

        // ---- O += P V  and  row sums via ones-MMA (exact fp32) ----
        float lsum[4] = {0.f, 0.f, 0.f, 0.f};
#pragma unroll
        for (int kk = 0; kk < 8; kk++) {
            uint32_t aH[4];
            aH[0] = p[2 * kk][0];
            aH[1] = p[2 * kk][1];
            aH[2] = p[2 * kk + 1][0];
            aH[3] = p[2 * kk + 1][1];
            mma_fp(lsum, aH, bones);           // lsum[0]=row0 sum, lsum[2]=row1 sum
#pragma unroll
            for (int np = 0; np < 4; np++) {
                uint32_t bv[4];
                const uint32_t off = (uint32_t)(kk * 16 + trow) * (FST * 2)
                                   + (uint32_t)(np * 16 + tcol) * 2;
                ldmat4t(bv, sV + off);
                mma_fp(o[np * 2],     aH, &bv[0]);
                mma_fp(o[np * 2 + 1], aH, &bv[2]);
            }
        }
        l0 = l0 * c0 + lsum[0];
        l1 = l1 * c1 + lsum[2];

        __syncthreads();
        if (jt + 2 < nkt)
            load_kv(stg, (jt + 2) * FBK, tid, gK, gV);
    }

    // ---- epilogue: normalize, split-fp16, write g_Ah/g_Al ----
    const float inv0 = 1.f / l0, inv1 = 1.f / l1;
#pragma unroll
    for (int nb = 0; nb < 8; nb++) {
        const int d0 = h * D_HEAD + nb * 8 + (lane & 3) * 2;
#pragma unroll
        for (int half_m = 0; half_m < 2; half_m++) {
            const int row = half_m ? row1 : row0;
            const float inv = half_m ? inv1 : inv0;
            const float v0 = o[nb][half_m * 2] * inv;
            const float v1 = o[nb][half_m * 2 + 1] * inv;
            const uint32_t uh = pack2(v0, v1);
            float2 f = unpack2(uh);
            const uint32_t ul = pack2(v0 - f.x, v1 - f.y);
            const size_t e = (size_t)(b * SEQ + row) * D_MODEL + d0;
            *(uint32_t*)(g_Ah + e) = uh;
            *(uint32_t*)(g_Al + e) = ul;
        }
    }
}

// ---------------- launch ----------------
extern "C" void kernel_launch(void* const* d_in, const int* in_sizes, int n_in,
                              void* d_out, int out_size)
{
    const float* x  = (const float*)d_in[0];
    const float* Wq = (const float*)d_in[1];
    const float* bq = (const float*)d_in[2];
    const float* Wk = (const float*)d_in[3];
    const float* bk = (const float*)d_in[4];
    const float* Wv = (const float*)d_in[5];
    const float* bv = (const float*)d_in[6];
    const float* Wo = (const float*)d_in[7];
    float* out = (float*)d_out;

    const int qkvSmem = 2 * QSTAGE;                                   // 184320
    cudaFuncSetAttribute(gemm_qkv, cudaFuncAttributeMaxDynamicSharedMemorySize, qkvSmem);
    const int woSmem = 2 * WSTAGE;                                    // 61440
    cudaFuncSetAttribute(gemm_wo, cudaFuncAttributeMaxDynamicSharedMemorySize, woSmem);
    const int flashSmem = (2 * QTILE + 2 * KVSTG) * (int)sizeof(__half);  // 110592
    cudaFuncSetAttribute(flash_mma, cudaFuncAttributeMaxDynamicSharedMemorySize, flashSmem);

    cvt_rm<<<M_ROWS * D_MODEL / 4 / 256, 256>>>(x);
    cvt_wt<<<dim3(D_MODEL / 32, D_MODEL / 32, 4), 256>>>(Wq, Wk, Wv, Wo);
    gemm_qkv<<<dim3(D_MODEL / 128, M_ROWS / 128), 256, qkvSmem>>>(bq, bk, bv);
    flash_mma<<<dim3(SEQ / 128, N_HEADS, BATCH), 256, flashSmem>>>();
    gemm_wo<<<dim3(D_MODEL / 128, M_ROWS / 128), 256, woSmem>>>(out);
}